// round 1
// baseline (speedup 1.0000x reference)
#include <cuda_runtime.h>
#include <math.h>

#define B_  4
#define S_  2048
#define D_  1024
#define H_  16
#define HD_ 64
#define F_  4096
#define NT_ (B_*S_)   // 8192 tokens

// ---------------- scratch (no allocation allowed) ----------------
__device__ float g_h  [(size_t)NT_*D_];
__device__ float g_q  [(size_t)NT_*D_];
__device__ float g_k  [(size_t)NT_*D_];
__device__ float g_v  [(size_t)NT_*D_];
__device__ float g_ctx[(size_t)NT_*D_];
__device__ float g_G  [(size_t)NT_*F_];
__device__ float g_U  [(size_t)NT_*F_];

// ---------------- RMSNorm: one block per row of 1024 ----------------
__global__ void rmsnorm_kernel(const float* __restrict__ x,
                               const float* __restrict__ scale,
                               float* __restrict__ out) {
    int row = blockIdx.x;
    int t = threadIdx.x;                    // 256 threads, 4 floats each
    const float4* xr = (const float4*)(x + (size_t)row * D_);
    float4 v = xr[t];
    float ss = v.x*v.x + v.y*v.y + v.z*v.z + v.w*v.w;
    #pragma unroll
    for (int o = 16; o; o >>= 1) ss += __shfl_xor_sync(0xffffffffu, ss, o);
    __shared__ float red[8];
    if ((t & 31) == 0) red[t >> 5] = ss;
    __syncthreads();
    if (t < 8) {
        float s2 = red[t];
        s2 += __shfl_xor_sync(0xffu, s2, 4);
        s2 += __shfl_xor_sync(0xffu, s2, 2);
        s2 += __shfl_xor_sync(0xffu, s2, 1);
        if (t == 0) red[0] = s2;
    }
    __syncthreads();
    float inv = rsqrtf(red[0] * (1.0f / D_) + 1e-6f);
    float4 s4 = ((const float4*)scale)[t];
    float4 o4;
    o4.x = v.x * inv * s4.x;
    o4.y = v.y * inv * s4.y;
    o4.z = v.z * inv * s4.z;
    o4.w = v.w * inv * s4.w;
    ((float4*)(out + (size_t)row * D_))[t] = o4;
}

// ---------------- SGEMM: C[M,N] = A[M,K] @ B[K,N] (+ Res) ----------------
// BM=BN=128, BK=16, 256 threads, 8x8 micro-tile.
template<int ADD_RES>
__global__ __launch_bounds__(256, 2)
void sgemm_kernel(const float* __restrict__ A, const float* __restrict__ B,
                  const float* __restrict__ Res, float* __restrict__ C,
                  int M, int N, int K) {
    const int BK = 16;
    __shared__ float As[BK][128 + 4];   // stored transposed: As[k][m]
    __shared__ float Bs[BK][128 + 4];

    int tid = threadIdx.x;
    int tx = tid & 15, ty = tid >> 4;
    int m0 = blockIdx.y * 128, n0 = blockIdx.x * 128;

    float acc[8][8];
    #pragma unroll
    for (int i = 0; i < 8; i++)
        #pragma unroll
        for (int j = 0; j < 8; j++) acc[i][j] = 0.f;

    int aRow = tid >> 2;            // 0..63
    int aCol = (tid & 3) * 4;       // 0,4,8,12
    int bRow = tid >> 5;            // 0..7
    int bCol = (tid & 31) * 4;      // 0..124

    const float* Aptr = A + (size_t)(m0 + aRow) * K + aCol;
    const float* Bptr = B + (size_t)bRow * N + n0 + bCol;

    for (int kt = 0; kt < K; kt += BK) {
        float4 a0 = *(const float4*)(Aptr);
        float4 a1 = *(const float4*)(Aptr + (size_t)64 * K);
        float4 b0 = *(const float4*)(Bptr);
        float4 b1 = *(const float4*)(Bptr + (size_t)8 * N);

        As[aCol+0][aRow]    = a0.x; As[aCol+1][aRow]    = a0.y;
        As[aCol+2][aRow]    = a0.z; As[aCol+3][aRow]    = a0.w;
        As[aCol+0][aRow+64] = a1.x; As[aCol+1][aRow+64] = a1.y;
        As[aCol+2][aRow+64] = a1.z; As[aCol+3][aRow+64] = a1.w;
        *(float4*)&Bs[bRow][bCol]   = b0;
        *(float4*)&Bs[bRow+8][bCol] = b1;
        __syncthreads();

        #pragma unroll
        for (int kk = 0; kk < BK; kk++) {
            float4 a_0 = *(const float4*)&As[kk][ty*8];
            float4 a_1 = *(const float4*)&As[kk][ty*8+4];
            float4 b_0 = *(const float4*)&Bs[kk][tx*8];
            float4 b_1 = *(const float4*)&Bs[kk][tx*8+4];
            float ar[8] = {a_0.x,a_0.y,a_0.z,a_0.w,a_1.x,a_1.y,a_1.z,a_1.w};
            float br[8] = {b_0.x,b_0.y,b_0.z,b_0.w,b_1.x,b_1.y,b_1.z,b_1.w};
            #pragma unroll
            for (int i = 0; i < 8; i++)
                #pragma unroll
                for (int j = 0; j < 8; j++)
                    acc[i][j] = fmaf(ar[i], br[j], acc[i][j]);
        }
        __syncthreads();
        Aptr += BK;
        Bptr += (size_t)BK * N;
    }

    #pragma unroll
    for (int i = 0; i < 8; i++) {
        size_t r = (size_t)(m0 + ty*8 + i);
        float* cp = C + r * N + n0 + tx*8;
        float4 o0 = {acc[i][0], acc[i][1], acc[i][2], acc[i][3]};
        float4 o1 = {acc[i][4], acc[i][5], acc[i][6], acc[i][7]};
        if (ADD_RES) {
            const float* rp = Res + r * N + n0 + tx*8;
            float4 r0 = *(const float4*)rp;
            float4 r1 = *(const float4*)(rp + 4);
            o0.x += r0.x; o0.y += r0.y; o0.z += r0.z; o0.w += r0.w;
            o1.x += r1.x; o1.y += r1.y; o1.z += r1.z; o1.w += r1.w;
        }
        *(float4*)cp       = o0;
        *(float4*)(cp + 4) = o1;
    }
}

// ---------------- RoPE (+optional 1/sqrt(hd) scale) ----------------
__global__ void rope_kernel(float* __restrict__ qk,
                            const int* __restrict__ pos, float scale) {
    int idx = blockIdx.x * 256 + threadIdx.x;   // NT_*H_*32 threads
    int i = idx & 31;
    int h = (idx >> 5) & (H_ - 1);
    int t = idx >> 9;
    float p = (float)pos[t];
    float frac = (float)(2 * i) / (float)HD_;
    float ts = powf(10000.0f, frac);
    float ang = p / ts;
    float sn, cs;
    sincosf(ang, &sn, &cs);
    float* base = qk + (size_t)t * D_ + h * HD_;
    float x1 = base[i], x2 = base[i + 32];
    base[i]      = (x1 * cs - x2 * sn) * scale;
    base[i + 32] = (x2 * cs + x1 * sn) * scale;
}

// ---------------- causal flash attention (fp32) ----------------
// One block per (q-tile of 64, b*h). 256 threads, strided 4x4 micro-tiles.
// Smem: Qs[64][64], Ks[64][64] (XOR-swizzled, reused for P), Vs[64][64] = 48KB.
__global__ __launch_bounds__(256)
void flash_kernel(const float* __restrict__ Q, const float* __restrict__ K,
                  const float* __restrict__ V, float* __restrict__ O) {
    __shared__ float Qs[64 * 64];
    __shared__ float Ks[64 * 64];   // K tile (swizzled), then P tile (swizzled)
    __shared__ float Vs[64 * 64];

    int qt  = blockIdx.x;           // 0..31
    int bh  = blockIdx.y;           // 0..63
    int b   = bh >> 4, h = bh & 15;
    int tid = threadIdx.x;
    int tx  = tid & 15, ty = tid >> 4;
    int qbase = qt * 64;

    const float* Qg = Q + ((size_t)(b * S_ + qbase)) * D_ + h * HD_;

    // load Q tile (row-major, no swizzle needed: reads are broadcast)
    #pragma unroll
    for (int s = 0; s < 4; s++) {
        int r  = (tid >> 4) + 16 * s;
        int c4 = (tid & 15) * 4;
        *(float4*)&Qs[r * 64 + c4] = *(const float4*)(Qg + (size_t)r * D_ + c4);
    }

    float m_i[4], l_i[4], acc_o[4][4];
    #pragma unroll
    for (int i = 0; i < 4; i++) {
        m_i[i] = -3.0e38f; l_i[i] = 0.f;
        #pragma unroll
        for (int j = 0; j < 4; j++) acc_o[i][j] = 0.f;
    }

    for (int jt = 0; jt <= qt; jt++) {
        int kbase = jt * 64;
        const float* Kg = K + ((size_t)(b * S_ + kbase)) * D_ + h * HD_;
        const float* Vg = V + ((size_t)(b * S_ + kbase)) * D_ + h * HD_;

        __syncthreads();   // previous iter's P/V reads done
        #pragma unroll
        for (int s = 0; s < 4; s++) {
            int r  = (tid >> 4) + 16 * s;
            int c4 = (tid & 15) * 4;
            float4 kv = *(const float4*)(Kg + (size_t)r * D_ + c4);
            int slot = (c4 >> 2) ^ (r & 15);            // XOR swizzle
            *(float4*)&Ks[r * 64 + (slot << 2)] = kv;
            float4 vv = *(const float4*)(Vg + (size_t)r * D_ + c4);
            *(float4*)&Vs[r * 64 + c4] = vv;
        }
        __syncthreads();

        // S = Q K^T  (vectorized over d, strided micro-tile)
        float s_acc[4][4];
        #pragma unroll
        for (int i = 0; i < 4; i++)
            #pragma unroll
            for (int j = 0; j < 4; j++) s_acc[i][j] = 0.f;

        #pragma unroll
        for (int d4 = 0; d4 < 64; d4 += 4) {
            float4 qf[4], kf[4];
            #pragma unroll
            for (int i = 0; i < 4; i++)
                qf[i] = *(const float4*)&Qs[(ty + 16*i) * 64 + d4];
            int sl = ((d4 >> 2) ^ tx) << 2;
            #pragma unroll
            for (int j = 0; j < 4; j++) {
                int c = tx + 16*j;
                kf[j] = *(const float4*)&Ks[c * 64 + sl];
            }
            #pragma unroll
            for (int i = 0; i < 4; i++)
                #pragma unroll
                for (int j = 0; j < 4; j++) {
                    s_acc[i][j] = fmaf(qf[i].x, kf[j].x, s_acc[i][j]);
                    s_acc[i][j] = fmaf(qf[i].y, kf[j].y, s_acc[i][j]);
                    s_acc[i][j] = fmaf(qf[i].z, kf[j].z, s_acc[i][j]);
                    s_acc[i][j] = fmaf(qf[i].w, kf[j].w, s_acc[i][j]);
                }
        }

        // causal mask on diagonal tile
        if (jt == qt) {
            #pragma unroll
            for (int i = 0; i < 4; i++)
                #pragma unroll
                for (int j = 0; j < 4; j++)
                    if (tx + 16*j > ty + 16*i) s_acc[i][j] = -1.0e30f;
        }

        // online softmax (rows replicated across the 16 tx lanes)
        #pragma unroll
        for (int i = 0; i < 4; i++) {
            float rm = fmaxf(fmaxf(s_acc[i][0], s_acc[i][1]),
                             fmaxf(s_acc[i][2], s_acc[i][3]));
            rm = fmaxf(rm, __shfl_xor_sync(0xffffffffu, rm, 8));
            rm = fmaxf(rm, __shfl_xor_sync(0xffffffffu, rm, 4));
            rm = fmaxf(rm, __shfl_xor_sync(0xffffffffu, rm, 2));
            rm = fmaxf(rm, __shfl_xor_sync(0xffffffffu, rm, 1));
            float mn   = fmaxf(m_i[i], rm);
            float corr = __expf(m_i[i] - mn);
            m_i[i] = mn;
            l_i[i] *= corr;
            #pragma unroll
            for (int j = 0; j < 4; j++) acc_o[i][j] *= corr;
            float rs = 0.f;
            #pragma unroll
            for (int j = 0; j < 4; j++) {
                float p = __expf(s_acc[i][j] - mn);
                s_acc[i][j] = p;
                rs += p;
            }
            rs += __shfl_xor_sync(0xffffffffu, rs, 8);
            rs += __shfl_xor_sync(0xffffffffu, rs, 4);
            rs += __shfl_xor_sync(0xffffffffu, rs, 2);
            rs += __shfl_xor_sync(0xffffffffu, rs, 1);
            l_i[i] += rs;
        }

        __syncthreads();   // all S reads of Ks done before overwrite with P
        // store P into Ks buffer: Ps[key][r] with r-index XOR swizzle
        #pragma unroll
        for (int i = 0; i < 4; i++)
            #pragma unroll
            for (int j = 0; j < 4; j++) {
                int key = tx + 16*j;
                int r   = ty + 16*i;
                int rp  = (r & 48) | ((r & 15) ^ (key & 15));
                Ks[key * 64 + rp] = s_acc[i][j];
            }
        __syncthreads();

        // O += P V
        #pragma unroll 4
        for (int kk = 0; kk < 64; kk++) {
            float a[4], bv[4];
            #pragma unroll
            for (int i = 0; i < 4; i++) {
                int r  = ty + 16*i;
                int rp = (r & 48) | ((r & 15) ^ (kk & 15));
                a[i] = Ks[kk * 64 + rp];
            }
            #pragma unroll
            for (int j = 0; j < 4; j++) bv[j] = Vs[kk * 64 + tx + 16*j];
            #pragma unroll
            for (int i = 0; i < 4; i++)
                #pragma unroll
                for (int j = 0; j < 4; j++)
                    acc_o[i][j] = fmaf(a[i], bv[j], acc_o[i][j]);
        }
    }

    float* Og = O + ((size_t)(b * S_ + qbase)) * D_ + h * HD_;
    #pragma unroll
    for (int i = 0; i < 4; i++) {
        float inv = 1.0f / l_i[i];
        #pragma unroll
        for (int j = 0; j < 4; j++)
            Og[(size_t)(ty + 16*i) * D_ + tx + 16*j] = acc_o[i][j] * inv;
    }
}

// ---------------- gelu(G)*U ----------------
__global__ void gelu_mul_kernel(const float* __restrict__ G,
                                const float* __restrict__ U,
                                float* __restrict__ Out) {
    int i = blockIdx.x * 256 + threadIdx.x;
    float4 g = ((const float4*)G)[i];
    float4 u = ((const float4*)U)[i];
    const float c0 = 0.7978845608028654f;   // sqrt(2/pi)
    const float c1 = 0.044715f;
    float4 o;
    o.x = 0.5f * g.x * (1.f + tanhf(c0 * (g.x + c1 * g.x * g.x * g.x))) * u.x;
    o.y = 0.5f * g.y * (1.f + tanhf(c0 * (g.y + c1 * g.y * g.y * g.y))) * u.y;
    o.z = 0.5f * g.z * (1.f + tanhf(c0 * (g.z + c1 * g.z * g.z * g.z))) * u.z;
    o.w = 0.5f * g.w * (1.f + tanhf(c0 * (g.w + c1 * g.w * g.w * g.w))) * u.w;
    ((float4*)Out)[i] = o;
}

// ---------------- launch ----------------
extern "C" void kernel_launch(void* const* d_in, const int* in_sizes, int n_in,
                              void* d_out, int out_size) {
    const float* x   = (const float*)d_in[0];
    const int*   sp  = (const int*)  d_in[1];
    // d_in[2] = mask (causal tril, hardcoded in flash kernel)
    const float* wq  = (const float*)d_in[3];
    const float* wk  = (const float*)d_in[4];
    const float* wv  = (const float*)d_in[5];
    const float* wo  = (const float*)d_in[6];
    const float* wg  = (const float*)d_in[7];
    const float* wu  = (const float*)d_in[8];
    const float* wd  = (const float*)d_in[9];
    const float* n1  = (const float*)d_in[10];
    const float* n2  = (const float*)d_in[11];
    float* out = (float*)d_out;

    float *h, *q, *k, *v, *ctx, *G, *U;
    cudaGetSymbolAddress((void**)&h,   g_h);
    cudaGetSymbolAddress((void**)&q,   g_q);
    cudaGetSymbolAddress((void**)&k,   g_k);
    cudaGetSymbolAddress((void**)&v,   g_v);
    cudaGetSymbolAddress((void**)&ctx, g_ctx);
    cudaGetSymbolAddress((void**)&G,   g_G);
    cudaGetSymbolAddress((void**)&U,   g_U);

    // attention block
    rmsnorm_kernel<<<NT_, 256>>>(x, n1, h);
    dim3 gQ(D_ / 128, NT_ / 128);
    sgemm_kernel<0><<<gQ, 256>>>(h, wq, nullptr, q, NT_, D_, D_);
    sgemm_kernel<0><<<gQ, 256>>>(h, wk, nullptr, k, NT_, D_, D_);
    sgemm_kernel<0><<<gQ, 256>>>(h, wv, nullptr, v, NT_, D_, D_);
    int ropeBlocks = NT_ * H_ * 32 / 256;
    rope_kernel<<<ropeBlocks, 256>>>(q, sp, 0.125f);   // 1/sqrt(64)
    rope_kernel<<<ropeBlocks, 256>>>(k, sp, 1.0f);
    flash_kernel<<<dim3(S_ / 64, B_ * H_), 256>>>(q, k, v, ctx);
    sgemm_kernel<1><<<gQ, 256>>>(ctx, wo, x, out, NT_, D_, D_);

    // FFN block
    rmsnorm_kernel<<<NT_, 256>>>(out, n2, h);
    dim3 gF(F_ / 128, NT_ / 128);
    sgemm_kernel<0><<<gF, 256>>>(h, wg, nullptr, G, NT_, F_, D_);
    sgemm_kernel<0><<<gF, 256>>>(h, wu, nullptr, U, NT_, F_, D_);
    gelu_mul_kernel<<<(size_t)NT_ * F_ / 1024, 256>>>(G, U, G);
    sgemm_kernel<1><<<gQ, 256>>>(G, wd, out, out, NT_, D_, F_);
}

// round 2
// speedup vs baseline: 1.6124x; 1.6124x over previous
#include <cuda_runtime.h>
#include <math.h>
#include <stdint.h>

#define B_  4
#define S_  2048
#define D_  1024
#define H_  16
#define HD_ 64
#define F_  4096
#define NT_ (B_*S_)   // 8192 tokens

// ---------------- scratch (no allocation allowed) ----------------
__device__ float g_h  [(size_t)NT_*D_];
__device__ float g_q  [(size_t)NT_*D_];
__device__ float g_k  [(size_t)NT_*D_];
__device__ float g_v  [(size_t)NT_*D_];
__device__ float g_ctx[(size_t)NT_*D_];
__device__ float g_G  [(size_t)NT_*F_];
__device__ float g_U  [(size_t)NT_*F_];

// ---------------- RMSNorm ----------------
__global__ void rmsnorm_kernel(const float* __restrict__ x,
                               const float* __restrict__ scale,
                               float* __restrict__ out) {
    int row = blockIdx.x;
    int t = threadIdx.x;
    const float4* xr = (const float4*)(x + (size_t)row * D_);
    float4 v = xr[t];
    float ss = v.x*v.x + v.y*v.y + v.z*v.z + v.w*v.w;
    #pragma unroll
    for (int o = 16; o; o >>= 1) ss += __shfl_xor_sync(0xffffffffu, ss, o);
    __shared__ float red[8];
    if ((t & 31) == 0) red[t >> 5] = ss;
    __syncthreads();
    if (t < 8) {
        float s2 = red[t];
        s2 += __shfl_xor_sync(0xffu, s2, 4);
        s2 += __shfl_xor_sync(0xffu, s2, 2);
        s2 += __shfl_xor_sync(0xffu, s2, 1);
        if (t == 0) red[0] = s2;
    }
    __syncthreads();
    float inv = rsqrtf(red[0] * (1.0f / D_) + 1e-6f);
    float4 s4 = ((const float4*)scale)[t];
    float4 o4;
    o4.x = v.x * inv * s4.x;
    o4.y = v.y * inv * s4.y;
    o4.z = v.z * inv * s4.z;
    o4.w = v.w * inv * s4.w;
    ((float4*)(out + (size_t)row * D_))[t] = o4;
}

// ---------------- TF32 tensor-core GEMM ----------------
// C[M,N] = A[M,K] @ B[K,N] (+Res), BM=BN=128, BK=16, 256 threads.
// mma.sync.m16n8k8 tf32. Smem holds pre-permuted fragments:
//  A frag (16x8): lane=(m%8)*4+(k%4), slot=((k%8)/4)*2+(m%16)/8 -> LDS.128/frag
//  B frag (8x8):  lane=(n%8)*4+(k%4), slot=(k%8)/4             -> LDS.64/frag

__device__ __forceinline__ uint32_t f2tf(float x) {
    uint32_t r;
    asm("cvt.rna.tf32.f32 %0, %1;" : "=r"(r) : "f"(x));
    return r;
}

__device__ __forceinline__ void mma_tf32(float* c, const uint4& a, const uint2& b) {
    asm volatile(
        "mma.sync.aligned.m16n8k8.row.col.f32.tf32.tf32.f32 "
        "{%0,%1,%2,%3}, {%4,%5,%6,%7}, {%8,%9}, {%0,%1,%2,%3};"
        : "+f"(c[0]), "+f"(c[1]), "+f"(c[2]), "+f"(c[3])
        : "r"(a.x), "r"(a.y), "r"(a.z), "r"(a.w), "r"(b.x), "r"(b.y));
}

template<int ADD_RES>
__global__ __launch_bounds__(256, 2)
void mma_gemm(const float* __restrict__ A, const float* __restrict__ B,
              const float* __restrict__ Res, float* __restrict__ C,
              int M, int N, int K) {
    __shared__ uint32_t AF[2][2][8][128];   // [buf][kstep][mfrag][lane*4+slot]
    __shared__ uint32_t BF[2][2][16][64];   // [buf][kstep][nfrag][lane*2+slot]

    const int tid  = threadIdx.x;
    const int lane = tid & 31;
    const int warp = tid >> 5;
    const int wm = warp >> 2;        // 0..1
    const int wn = warp & 3;         // 0..3
    const int m0 = blockIdx.y * 128;
    const int n0 = blockIdx.x * 128;

    // writer assignment
    const int am = tid >> 1;              // 0..127
    const int ak = (tid & 1) * 4;         // 0 or 4
    const int bk = tid >> 5;              // 0..7
    const int bn = (tid & 31) * 4;        // 0..124

    const float* Ap = A + (size_t)(m0 + am) * K + ak;
    const float* Bp = B + (size_t)bk * N + n0 + bn;

    // precomputed STS indices
    const int a_mf   = am >> 4;
    const int a_lane = (am & 7) * 4;
    const int a_mhi  = (am >> 3) & 1;
    const int b_nf   = bn >> 3;
    const int b_lane = (bn & 7) * 4 + (bk & 3);
    const int b_slot = (bk >> 2) & 1;

    float acc[4][4][4];
    #pragma unroll
    for (int i = 0; i < 4; i++)
        #pragma unroll
        for (int j = 0; j < 4; j++)
            #pragma unroll
            for (int c = 0; c < 4; c++) acc[i][j][c] = 0.f;

    float4 ar0, ar1, br0, br1;
    ar0 = *(const float4*)Ap;
    ar1 = *(const float4*)(Ap + 8);
    br0 = *(const float4*)Bp;
    br1 = *(const float4*)(Bp + (size_t)8 * N);

    const int nt = K >> 4;

    #define STS_TILE(BUF)                                                      \
    do {                                                                       \
        /* A: (am, ak..ak+3) kstep=0 ; (am, ak+8..) kstep=1 */                 \
        {                                                                      \
            int slot = (((ak & 7) >> 2) << 1) | a_mhi;                         \
            uint32_t* p0 = &AF[BUF][0][a_mf][0];                               \
            p0[(a_lane+0)*4 + slot] = f2tf(ar0.x);                             \
            p0[(a_lane+1)*4 + slot] = f2tf(ar0.y);                             \
            p0[(a_lane+2)*4 + slot] = f2tf(ar0.z);                             \
            p0[(a_lane+3)*4 + slot] = f2tf(ar0.w);                             \
            uint32_t* p1 = &AF[BUF][1][a_mf][0];                               \
            p1[(a_lane+0)*4 + slot] = f2tf(ar1.x);                             \
            p1[(a_lane+1)*4 + slot] = f2tf(ar1.y);                             \
            p1[(a_lane+2)*4 + slot] = f2tf(ar1.z);                             \
            p1[(a_lane+3)*4 + slot] = f2tf(ar1.w);                             \
        }                                                                      \
        {                                                                      \
            uint32_t* p0 = &BF[BUF][0][b_nf][0];                               \
            int idx = b_lane * 2 + b_slot;                                     \
            p0[idx]      = f2tf(br0.x);                                        \
            p0[idx + 8]  = f2tf(br0.y);                                        \
            p0[idx + 16] = f2tf(br0.z);                                        \
            p0[idx + 24] = f2tf(br0.w);                                        \
            uint32_t* p1 = &BF[BUF][1][b_nf][0];                               \
            p1[idx]      = f2tf(br1.x);                                        \
            p1[idx + 8]  = f2tf(br1.y);                                        \
            p1[idx + 16] = f2tf(br1.z);                                        \
            p1[idx + 24] = f2tf(br1.w);                                        \
        }                                                                      \
    } while (0)

    STS_TILE(0);
    __syncthreads();

    for (int kt = 0; kt < nt; kt++) {
        int buf = kt & 1;
        if (kt + 1 < nt) {
            Ap += 16;
            Bp += (size_t)16 * N;
            ar0 = *(const float4*)Ap;
            ar1 = *(const float4*)(Ap + 8);
            br0 = *(const float4*)Bp;
            br1 = *(const float4*)(Bp + (size_t)8 * N);
        }
        // compute on buf
        #pragma unroll
        for (int s = 0; s < 2; s++) {
            uint4 af[4];
            uint2 bf[4];
            #pragma unroll
            for (int i = 0; i < 4; i++)
                af[i] = *(const uint4*)&AF[buf][s][wm*4 + i][lane*4];
            #pragma unroll
            for (int j = 0; j < 4; j++)
                bf[j] = *(const uint2*)&BF[buf][s][wn*4 + j][lane*2];
            #pragma unroll
            for (int i = 0; i < 4; i++)
                #pragma unroll
                for (int j = 0; j < 4; j++)
                    mma_tf32(acc[i][j], af[i], bf[j]);
        }
        if (kt + 1 < nt) {
            int nb = buf ^ 1;
            STS_TILE(nb);
            __syncthreads();
        }
    }
    #undef STS_TILE

    // epilogue
    const int g  = lane >> 2;
    const int tg = lane & 3;
    #pragma unroll
    for (int i = 0; i < 4; i++) {
        int row0 = m0 + wm*64 + i*16 + g;
        #pragma unroll
        for (int j = 0; j < 4; j++) {
            int col = n0 + wn*32 + j*8 + tg*2;
            float2 v0 = {acc[i][j][0], acc[i][j][1]};
            float2 v1 = {acc[i][j][2], acc[i][j][3]};
            float* c0 = C + (size_t)row0 * N + col;
            float* c1 = C + (size_t)(row0 + 8) * N + col;
            if (ADD_RES) {
                const float2 r0 = *(const float2*)(Res + (size_t)row0 * N + col);
                const float2 r1 = *(const float2*)(Res + (size_t)(row0 + 8) * N + col);
                v0.x += r0.x; v0.y += r0.y;
                v1.x += r1.x; v1.y += r1.y;
            }
            *(float2*)c0 = v0;
            *(float2*)c1 = v1;
        }
    }
}

// ---------------- RoPE ----------------
__global__ void rope_kernel(float* __restrict__ qk,
                            const int* __restrict__ pos, float scale) {
    int idx = blockIdx.x * 256 + threadIdx.x;
    int i = idx & 31;
    int h = (idx >> 5) & (H_ - 1);
    int t = idx >> 9;
    float p = (float)pos[t];
    float frac = (float)(2 * i) / (float)HD_;
    float ts = powf(10000.0f, frac);
    float ang = p / ts;
    float sn, cs;
    sincosf(ang, &sn, &cs);
    float* base = qk + (size_t)t * D_ + h * HD_;
    float x1 = base[i], x2 = base[i + 32];
    base[i]      = (x1 * cs - x2 * sn) * scale;
    base[i + 32] = (x2 * cs + x1 * sn) * scale;
}

// ---------------- causal flash attention (fp32) ----------------
__global__ __launch_bounds__(256)
void flash_kernel(const float* __restrict__ Q, const float* __restrict__ K,
                  const float* __restrict__ V, float* __restrict__ O) {
    __shared__ float Qs[64 * 64];
    __shared__ float Ks[64 * 64];
    __shared__ float Vs[64 * 64];

    int qt  = blockIdx.x;
    int bh  = blockIdx.y;
    int b   = bh >> 4, h = bh & 15;
    int tid = threadIdx.x;
    int tx  = tid & 15, ty = tid >> 4;
    int qbase = qt * 64;

    const float* Qg = Q + ((size_t)(b * S_ + qbase)) * D_ + h * HD_;

    #pragma unroll
    for (int s = 0; s < 4; s++) {
        int r  = (tid >> 4) + 16 * s;
        int c4 = (tid & 15) * 4;
        *(float4*)&Qs[r * 64 + c4] = *(const float4*)(Qg + (size_t)r * D_ + c4);
    }

    float m_i[4], l_i[4], acc_o[4][4];
    #pragma unroll
    for (int i = 0; i < 4; i++) {
        m_i[i] = -3.0e38f; l_i[i] = 0.f;
        #pragma unroll
        for (int j = 0; j < 4; j++) acc_o[i][j] = 0.f;
    }

    for (int jt = 0; jt <= qt; jt++) {
        int kbase = jt * 64;
        const float* Kg = K + ((size_t)(b * S_ + kbase)) * D_ + h * HD_;
        const float* Vg = V + ((size_t)(b * S_ + kbase)) * D_ + h * HD_;

        __syncthreads();
        #pragma unroll
        for (int s = 0; s < 4; s++) {
            int r  = (tid >> 4) + 16 * s;
            int c4 = (tid & 15) * 4;
            float4 kv = *(const float4*)(Kg + (size_t)r * D_ + c4);
            int slot = (c4 >> 2) ^ (r & 15);
            *(float4*)&Ks[r * 64 + (slot << 2)] = kv;
            float4 vv = *(const float4*)(Vg + (size_t)r * D_ + c4);
            *(float4*)&Vs[r * 64 + c4] = vv;
        }
        __syncthreads();

        float s_acc[4][4];
        #pragma unroll
        for (int i = 0; i < 4; i++)
            #pragma unroll
            for (int j = 0; j < 4; j++) s_acc[i][j] = 0.f;

        #pragma unroll
        for (int d4 = 0; d4 < 64; d4 += 4) {
            float4 qf[4], kf[4];
            #pragma unroll
            for (int i = 0; i < 4; i++)
                qf[i] = *(const float4*)&Qs[(ty + 16*i) * 64 + d4];
            int sl = ((d4 >> 2) ^ tx) << 2;
            #pragma unroll
            for (int j = 0; j < 4; j++) {
                int c = tx + 16*j;
                kf[j] = *(const float4*)&Ks[c * 64 + sl];
            }
            #pragma unroll
            for (int i = 0; i < 4; i++)
                #pragma unroll
                for (int j = 0; j < 4; j++) {
                    s_acc[i][j] = fmaf(qf[i].x, kf[j].x, s_acc[i][j]);
                    s_acc[i][j] = fmaf(qf[i].y, kf[j].y, s_acc[i][j]);
                    s_acc[i][j] = fmaf(qf[i].z, kf[j].z, s_acc[i][j]);
                    s_acc[i][j] = fmaf(qf[i].w, kf[j].w, s_acc[i][j]);
                }
        }

        if (jt == qt) {
            #pragma unroll
            for (int i = 0; i < 4; i++)
                #pragma unroll
                for (int j = 0; j < 4; j++)
                    if (tx + 16*j > ty + 16*i) s_acc[i][j] = -1.0e30f;
        }

        #pragma unroll
        for (int i = 0; i < 4; i++) {
            float rm = fmaxf(fmaxf(s_acc[i][0], s_acc[i][1]),
                             fmaxf(s_acc[i][2], s_acc[i][3]));
            rm = fmaxf(rm, __shfl_xor_sync(0xffffffffu, rm, 8));
            rm = fmaxf(rm, __shfl_xor_sync(0xffffffffu, rm, 4));
            rm = fmaxf(rm, __shfl_xor_sync(0xffffffffu, rm, 2));
            rm = fmaxf(rm, __shfl_xor_sync(0xffffffffu, rm, 1));
            float mn   = fmaxf(m_i[i], rm);
            float corr = __expf(m_i[i] - mn);
            m_i[i] = mn;
            l_i[i] *= corr;
            #pragma unroll
            for (int j = 0; j < 4; j++) acc_o[i][j] *= corr;
            float rs = 0.f;
            #pragma unroll
            for (int j = 0; j < 4; j++) {
                float p = __expf(s_acc[i][j] - mn);
                s_acc[i][j] = p;
                rs += p;
            }
            rs += __shfl_xor_sync(0xffffffffu, rs, 8);
            rs += __shfl_xor_sync(0xffffffffu, rs, 4);
            rs += __shfl_xor_sync(0xffffffffu, rs, 2);
            rs += __shfl_xor_sync(0xffffffffu, rs, 1);
            l_i[i] += rs;
        }

        __syncthreads();
        #pragma unroll
        for (int i = 0; i < 4; i++)
            #pragma unroll
            for (int j = 0; j < 4; j++) {
                int key = tx + 16*j;
                int r   = ty + 16*i;
                int rp  = (r & 48) | ((r & 15) ^ (key & 15));
                Ks[key * 64 + rp] = s_acc[i][j];
            }
        __syncthreads();

        #pragma unroll 4
        for (int kk = 0; kk < 64; kk++) {
            float a[4], bv[4];
            #pragma unroll
            for (int i = 0; i < 4; i++) {
                int r  = ty + 16*i;
                int rp = (r & 48) | ((r & 15) ^ (kk & 15));
                a[i] = Ks[kk * 64 + rp];
            }
            #pragma unroll
            for (int j = 0; j < 4; j++) bv[j] = Vs[kk * 64 + tx + 16*j];
            #pragma unroll
            for (int i = 0; i < 4; i++)
                #pragma unroll
                for (int j = 0; j < 4; j++)
                    acc_o[i][j] = fmaf(a[i], bv[j], acc_o[i][j]);
        }
    }

    float* Og = O + ((size_t)(b * S_ + qbase)) * D_ + h * HD_;
    #pragma unroll
    for (int i = 0; i < 4; i++) {
        float inv = 1.0f / l_i[i];
        #pragma unroll
        for (int j = 0; j < 4; j++)
            Og[(size_t)(ty + 16*i) * D_ + tx + 16*j] = acc_o[i][j] * inv;
    }
}

// ---------------- gelu(G)*U ----------------
__global__ void gelu_mul_kernel(const float* __restrict__ G,
                                const float* __restrict__ U,
                                float* __restrict__ Out) {
    int i = blockIdx.x * 256 + threadIdx.x;
    float4 g = ((const float4*)G)[i];
    float4 u = ((const float4*)U)[i];
    const float c0 = 0.7978845608028654f;
    const float c1 = 0.044715f;
    float4 o;
    o.x = 0.5f * g.x * (1.f + tanhf(c0 * (g.x + c1 * g.x * g.x * g.x))) * u.x;
    o.y = 0.5f * g.y * (1.f + tanhf(c0 * (g.y + c1 * g.y * g.y * g.y))) * u.y;
    o.z = 0.5f * g.z * (1.f + tanhf(c0 * (g.z + c1 * g.z * g.z * g.z))) * u.z;
    o.w = 0.5f * g.w * (1.f + tanhf(c0 * (g.w + c1 * g.w * g.w * g.w))) * u.w;
    ((float4*)Out)[i] = o;
}

// ---------------- launch ----------------
extern "C" void kernel_launch(void* const* d_in, const int* in_sizes, int n_in,
                              void* d_out, int out_size) {
    const float* x   = (const float*)d_in[0];
    const int*   sp  = (const int*)  d_in[1];
    const float* wq  = (const float*)d_in[3];
    const float* wk  = (const float*)d_in[4];
    const float* wv  = (const float*)d_in[5];
    const float* wo  = (const float*)d_in[6];
    const float* wg  = (const float*)d_in[7];
    const float* wu  = (const float*)d_in[8];
    const float* wd  = (const float*)d_in[9];
    const float* n1  = (const float*)d_in[10];
    const float* n2  = (const float*)d_in[11];
    float* out = (float*)d_out;

    float *h, *q, *k, *v, *ctx, *G, *U;
    cudaGetSymbolAddress((void**)&h,   g_h);
    cudaGetSymbolAddress((void**)&q,   g_q);
    cudaGetSymbolAddress((void**)&k,   g_k);
    cudaGetSymbolAddress((void**)&v,   g_v);
    cudaGetSymbolAddress((void**)&ctx, g_ctx);
    cudaGetSymbolAddress((void**)&G,   g_G);
    cudaGetSymbolAddress((void**)&U,   g_U);

    // attention block
    rmsnorm_kernel<<<NT_, 256>>>(x, n1, h);
    dim3 gQ(D_ / 128, NT_ / 128);
    mma_gemm<0><<<gQ, 256>>>(h, wq, nullptr, q, NT_, D_, D_);
    mma_gemm<0><<<gQ, 256>>>(h, wk, nullptr, k, NT_, D_, D_);
    mma_gemm<0><<<gQ, 256>>>(h, wv, nullptr, v, NT_, D_, D_);
    int ropeBlocks = NT_ * H_ * 32 / 256;
    rope_kernel<<<ropeBlocks, 256>>>(q, sp, 0.125f);
    rope_kernel<<<ropeBlocks, 256>>>(k, sp, 1.0f);
    flash_kernel<<<dim3(S_ / 64, B_ * H_), 256>>>(q, k, v, ctx);
    mma_gemm<1><<<gQ, 256>>>(ctx, wo, x, out, NT_, D_, D_);

    // FFN block
    rmsnorm_kernel<<<NT_, 256>>>(out, n2, h);
    dim3 gF(F_ / 128, NT_ / 128);
    mma_gemm<0><<<gF, 256>>>(h, wg, nullptr, G, NT_, F_, D_);
    mma_gemm<0><<<gF, 256>>>(h, wu, nullptr, U, NT_, F_, D_);
    gelu_mul_kernel<<<(size_t)NT_ * F_ / 1024, 256>>>(G, U, G);
    mma_gemm<1><<<gQ, 256>>>(G, wd, out, out, NT_, D_, F_);
}

// round 4
// speedup vs baseline: 4.1276x; 2.5599x over previous
#include <cuda_runtime.h>
#include <math.h>
#include <stdint.h>

#define B_  4
#define S_  2048
#define D_  1024
#define H_  16
#define HD_ 64
#define F_  4096
#define NT_ (B_*S_)   // 8192 tokens

// ---------------- scratch (no allocation allowed) ----------------
__device__ float g_h  [(size_t)NT_*D_];
__device__ float g_q  [(size_t)NT_*D_];
__device__ float g_k  [(size_t)NT_*D_];
__device__ float g_v  [(size_t)NT_*D_];
__device__ float g_ctx[(size_t)NT_*D_];
__device__ float g_G  [(size_t)NT_*F_];
__device__ float g_U  [(size_t)NT_*F_];
__device__ float g_wT [(size_t)4*D_*D_ + (size_t)3*D_*F_];

// ---------------- helpers ----------------
__device__ __forceinline__ uint32_t sm_u32(const void* p) {
    uint32_t a;
    asm("{ .reg .u64 t; cvta.to.shared.u64 t, %1; cvt.u32.u64 %0, t; }" : "=r"(a) : "l"(p));
    return a;
}
__device__ __forceinline__ void cp16(uint32_t dst, const void* src) {
    asm volatile("cp.async.cg.shared.global [%0], [%1], 16;" :: "r"(dst), "l"(src));
}
__device__ __forceinline__ void cp_commit() {
    asm volatile("cp.async.commit_group;" ::: "memory");
}
template<int N> __device__ __forceinline__ void cp_wait() {
    asm volatile("cp.async.wait_group %0;" :: "n"(N) : "memory");
}
__device__ __forceinline__ void ldm_x4(uint32_t& r0, uint32_t& r1, uint32_t& r2,
                                       uint32_t& r3, uint32_t addr) {
    asm volatile("ldmatrix.sync.aligned.m8n8.x4.shared.b16 {%0,%1,%2,%3}, [%4];"
                 : "=r"(r0), "=r"(r1), "=r"(r2), "=r"(r3) : "r"(addr));
}
__device__ __forceinline__ void mma_tf32(float* c, const uint32_t* a, const uint32_t* b) {
    asm volatile(
        "mma.sync.aligned.m16n8k8.row.col.f32.tf32.tf32.f32 "
        "{%0,%1,%2,%3}, {%4,%5,%6,%7}, {%8,%9}, {%0,%1,%2,%3};"
        : "+f"(c[0]), "+f"(c[1]), "+f"(c[2]), "+f"(c[3])
        : "r"(a[0]), "r"(a[1]), "r"(a[2]), "r"(a[3]), "r"(b[0]), "r"(b[1]));
}

// ---------------- TF32 mma.sync GEMM (CUTLASS-sm80 style) ----------------
// C[M,N] = A[M,K] @ Bt[N,K]^T (+Res). BM=BN=128, BK=32, 128 threads,
// warp tile 64x64, 3-stage cp.async, ldmatrix fragment loads.
#define BM 128
#define BN 128
#define BK 32
#define STAGES 3
#define ASTG (BM*BK*4)     // 16384 B
#define SSTG (2*ASTG)      // 32768 B per stage (A then B)
#define DSMEM (STAGES*SSTG)

template<int ADD_RES>
__global__ __launch_bounds__(128, 2)
void mma_gemm(const float* __restrict__ A, const float* __restrict__ Bt,
              const float* __restrict__ Res, float* __restrict__ C,
              int M, int N, int K) {
    extern __shared__ float smem[];
    const uint32_t sb = sm_u32(smem);
    const int tid  = threadIdx.x;
    const int lane = tid & 31;
    const int wid  = tid >> 5;
    const int wm   = wid >> 1;           // 0..1
    const int wn   = wid & 1;            // 0..1
    const int m0   = blockIdx.y * BM;
    const int n0   = blockIdx.x * BN;

    // --- cp.async mapping: thread t, rep i: chunk = t + 128*i ---
    // row = (t>>3) + 16*i, c = t&7  (c, row&7 constant over i)
    const int lrow = tid >> 3;
    const int lc   = tid & 7;
    const uint32_t dA0 = (uint32_t)lrow * 128 + (uint32_t)((lc ^ (lrow & 7)) << 4);
    const float* pA = A  + (size_t)(m0 + lrow) * K + lc * 4;
    const float* pB = Bt + (size_t)(n0 + lrow) * K + lc * 4;

    // --- ldmatrix row addresses (per fragment, per lane) ---
    const int q  = lane >> 3;
    const int r8 = lane & 7;
    const int qh = q >> 1;               // chunk offset bit
    const int ql = q & 1;                // +8 row bit
    uint32_t aRow[4], bRow[4];
    int am7[4], bn7[4];
    #pragma unroll
    for (int f = 0; f < 4; f++) {
        int m = wm * 64 + f * 16 + ql * 8 + r8;
        aRow[f] = (uint32_t)m * 128;
        am7[f]  = m & 7;
        int n = wn * 64 + f * 16 + ql * 8 + r8;
        bRow[f] = ASTG + (uint32_t)n * 128;
        bn7[f]  = n & 7;
    }

    float acc[4][8][4];
    #pragma unroll
    for (int i = 0; i < 4; i++)
        #pragma unroll
        for (int j = 0; j < 8; j++)
            #pragma unroll
            for (int c = 0; c < 4; c++) acc[i][j][c] = 0.f;

    const int nt = K / BK;
    const size_t stepA = (size_t)16 * K;   // row step between reps

    #define LOAD_TILE(stg, kt) do {                                           \
        uint32_t base = sb + (uint32_t)(stg) * SSTG;                          \
        size_t kk = (size_t)(kt) * BK;                                        \
        _Pragma("unroll")                                                     \
        for (int i = 0; i < 8; i++)                                           \
            cp16(base + dA0 + 2048u * i, pA + stepA * i + kk);                \
        _Pragma("unroll")                                                     \
        for (int i = 0; i < 8; i++)                                           \
            cp16(base + ASTG + dA0 + 2048u * i, pB + stepA * i + kk);         \
    } while (0)

    LOAD_TILE(0, 0); cp_commit();
    LOAD_TILE(1, 1); cp_commit();

    uint32_t a2[2][4][4], b2[2][8][2];

    #define LOAD_FRAGS(SB, s, buf) do {                                       \
        _Pragma("unroll")                                                     \
        for (int f = 0; f < 4; f++) {                                         \
            uint32_t ad = (SB) + aRow[f] + (uint32_t)(((2*(s)+qh) ^ am7[f]) << 4); \
            ldm_x4(a2[buf][f][0], a2[buf][f][1], a2[buf][f][2], a2[buf][f][3], ad); \
        }                                                                     \
        _Pragma("unroll")                                                     \
        for (int f = 0; f < 4; f++) {                                         \
            uint32_t bd = (SB) + bRow[f] + (uint32_t)(((2*(s)+qh) ^ bn7[f]) << 4); \
            ldm_x4(b2[buf][2*f][0], b2[buf][2*f+1][0],                        \
                   b2[buf][2*f][1], b2[buf][2*f+1][1], bd);                   \
        }                                                                     \
    } while (0)

    int stage = 0;
    for (int kt = 0; kt < nt; kt++) {
        cp_wait<1>();
        __syncthreads();
        int lk = kt + 2;
        if (lk < nt) {
            int lst = stage + 2; if (lst >= STAGES) lst -= STAGES;
            LOAD_TILE(lst, lk);
        }
        cp_commit();

        const uint32_t SB = sb + (uint32_t)stage * SSTG;
        LOAD_FRAGS(SB, 0, 0);
        #pragma unroll
        for (int s = 0; s < 4; s++) {
            if (s < 3) LOAD_FRAGS(SB, s + 1, (s + 1) & 1);
            int cur = s & 1;
            #pragma unroll
            for (int mf = 0; mf < 4; mf++)
                #pragma unroll
                for (int nf = 0; nf < 8; nf++)
                    mma_tf32(acc[mf][nf], a2[cur][mf], b2[cur][nf]);
        }
        if (++stage == STAGES) stage = 0;
    }
    #undef LOAD_FRAGS
    #undef LOAD_TILE

    // ---- epilogue ----
    const int g  = lane >> 2;
    const int tg = lane & 3;
    #pragma unroll
    for (int mf = 0; mf < 4; mf++) {
        int row = m0 + wm * 64 + mf * 16 + g;
        #pragma unroll
        for (int nf = 0; nf < 8; nf++) {
            int col = n0 + wn * 64 + nf * 8 + tg * 2;
            float2 v0 = {acc[mf][nf][0], acc[mf][nf][1]};
            float2 v1 = {acc[mf][nf][2], acc[mf][nf][3]};
            float* c0 = C + (size_t)row * N + col;
            float* c1 = C + (size_t)(row + 8) * N + col;
            if (ADD_RES) {
                float2 r0 = *(const float2*)(Res + (size_t)row * N + col);
                float2 r1 = *(const float2*)(Res + (size_t)(row + 8) * N + col);
                v0.x += r0.x; v0.y += r0.y;
                v1.x += r1.x; v1.y += r1.y;
            }
            *(float2*)c0 = v0;
            *(float2*)c1 = v1;
        }
    }
}

// ---------------- transpose: in[R][C] -> out[C][R] ----------------
__global__ void transpose_kernel(const float* __restrict__ in,
                                 float* __restrict__ out, int R, int C) {
    __shared__ float t[32][33];
    int bx = blockIdx.x * 32, by = blockIdx.y * 32;
    int x = bx + threadIdx.x;
    #pragma unroll
    for (int i = 0; i < 32; i += 8)
        t[threadIdx.y + i][threadIdx.x] = in[(size_t)(by + threadIdx.y + i) * C + x];
    __syncthreads();
    int xo = by + threadIdx.x;
    #pragma unroll
    for (int i = 0; i < 32; i += 8)
        out[(size_t)(bx + threadIdx.y + i) * R + xo] = t[threadIdx.x][threadIdx.y + i];
}

// ---------------- RMSNorm ----------------
__global__ void rmsnorm_kernel(const float* __restrict__ x,
                               const float* __restrict__ scale,
                               float* __restrict__ out) {
    int row = blockIdx.x;
    int t = threadIdx.x;
    const float4* xr = (const float4*)(x + (size_t)row * D_);
    float4 v = xr[t];
    float ss = v.x*v.x + v.y*v.y + v.z*v.z + v.w*v.w;
    #pragma unroll
    for (int o = 16; o; o >>= 1) ss += __shfl_xor_sync(0xffffffffu, ss, o);
    __shared__ float red[8];
    if ((t & 31) == 0) red[t >> 5] = ss;
    __syncthreads();
    if (t < 8) {
        float s2 = red[t];
        s2 += __shfl_xor_sync(0xffu, s2, 4);
        s2 += __shfl_xor_sync(0xffu, s2, 2);
        s2 += __shfl_xor_sync(0xffu, s2, 1);
        if (t == 0) red[0] = s2;
    }
    __syncthreads();
    float inv = rsqrtf(red[0] * (1.0f / D_) + 1e-6f);
    float4 s4 = ((const float4*)scale)[t];
    float4 o4;
    o4.x = v.x * inv * s4.x;
    o4.y = v.y * inv * s4.y;
    o4.z = v.z * inv * s4.z;
    o4.w = v.w * inv * s4.w;
    ((float4*)(out + (size_t)row * D_))[t] = o4;
}

// ---------------- RoPE ----------------
__global__ void rope_kernel(float* __restrict__ qk,
                            const int* __restrict__ pos, float scale) {
    int idx = blockIdx.x * 256 + threadIdx.x;
    int i = idx & 31;
    int h = (idx >> 5) & (H_ - 1);
    int t = idx >> 9;
    float p = (float)pos[t];
    float frac = (float)(2 * i) / (float)HD_;
    float ts = powf(10000.0f, frac);
    float ang = p / ts;
    float sn, cs;
    sincosf(ang, &sn, &cs);
    float* base = qk + (size_t)t * D_ + h * HD_;
    float x1 = base[i], x2 = base[i + 32];
    base[i]      = (x1 * cs - x2 * sn) * scale;
    base[i + 32] = (x2 * cs + x1 * sn) * scale;
}

// ---------------- causal flash attention (fp32) ----------------
__global__ __launch_bounds__(256)
void flash_kernel(const float* __restrict__ Q, const float* __restrict__ K,
                  const float* __restrict__ V, float* __restrict__ O) {
    __shared__ float Qs[64 * 64];
    __shared__ float Ks[64 * 64];
    __shared__ float Vs[64 * 64];

    int qt  = blockIdx.x;
    int bh  = blockIdx.y;
    int b   = bh >> 4, h = bh & 15;
    int tid = threadIdx.x;
    int tx  = tid & 15, ty = tid >> 4;
    int qbase = qt * 64;

    const float* Qg = Q + ((size_t)(b * S_ + qbase)) * D_ + h * HD_;

    #pragma unroll
    for (int s = 0; s < 4; s++) {
        int r  = (tid >> 4) + 16 * s;
        int c4 = (tid & 15) * 4;
        *(float4*)&Qs[r * 64 + c4] = *(const float4*)(Qg + (size_t)r * D_ + c4);
    }

    float m_i[4], l_i[4], acc_o[4][4];
    #pragma unroll
    for (int i = 0; i < 4; i++) {
        m_i[i] = -3.0e38f; l_i[i] = 0.f;
        #pragma unroll
        for (int j = 0; j < 4; j++) acc_o[i][j] = 0.f;
    }

    for (int jt = 0; jt <= qt; jt++) {
        int kbase = jt * 64;
        const float* Kg = K + ((size_t)(b * S_ + kbase)) * D_ + h * HD_;
        const float* Vg = V + ((size_t)(b * S_ + kbase)) * D_ + h * HD_;

        __syncthreads();
        #pragma unroll
        for (int s = 0; s < 4; s++) {
            int r  = (tid >> 4) + 16 * s;
            int c4 = (tid & 15) * 4;
            float4 kv = *(const float4*)(Kg + (size_t)r * D_ + c4);
            int slot = (c4 >> 2) ^ (r & 15);
            *(float4*)&Ks[r * 64 + (slot << 2)] = kv;
            float4 vv = *(const float4*)(Vg + (size_t)r * D_ + c4);
            *(float4*)&Vs[r * 64 + c4] = vv;
        }
        __syncthreads();

        float s_acc[4][4];
        #pragma unroll
        for (int i = 0; i < 4; i++)
            #pragma unroll
            for (int j = 0; j < 4; j++) s_acc[i][j] = 0.f;

        #pragma unroll
        for (int d4 = 0; d4 < 64; d4 += 4) {
            float4 qf[4], kf[4];
            #pragma unroll
            for (int i = 0; i < 4; i++)
                qf[i] = *(const float4*)&Qs[(ty + 16*i) * 64 + d4];
            int sl = ((d4 >> 2) ^ tx) << 2;
            #pragma unroll
            for (int j = 0; j < 4; j++) {
                int c = tx + 16*j;
                kf[j] = *(const float4*)&Ks[c * 64 + sl];
            }
            #pragma unroll
            for (int i = 0; i < 4; i++)
                #pragma unroll
                for (int j = 0; j < 4; j++) {
                    s_acc[i][j] = fmaf(qf[i].x, kf[j].x, s_acc[i][j]);
                    s_acc[i][j] = fmaf(qf[i].y, kf[j].y, s_acc[i][j]);
                    s_acc[i][j] = fmaf(qf[i].z, kf[j].z, s_acc[i][j]);
                    s_acc[i][j] = fmaf(qf[i].w, kf[j].w, s_acc[i][j]);
                }
        }

        if (jt == qt) {
            #pragma unroll
            for (int i = 0; i < 4; i++)
                #pragma unroll
                for (int j = 0; j < 4; j++)
                    if (tx + 16*j > ty + 16*i) s_acc[i][j] = -1.0e30f;
        }

        #pragma unroll
        for (int i = 0; i < 4; i++) {
            float rm = fmaxf(fmaxf(s_acc[i][0], s_acc[i][1]),
                             fmaxf(s_acc[i][2], s_acc[i][3]));
            rm = fmaxf(rm, __shfl_xor_sync(0xffffffffu, rm, 8));
            rm = fmaxf(rm, __shfl_xor_sync(0xffffffffu, rm, 4));
            rm = fmaxf(rm, __shfl_xor_sync(0xffffffffu, rm, 2));
            rm = fmaxf(rm, __shfl_xor_sync(0xffffffffu, rm, 1));
            float mn   = fmaxf(m_i[i], rm);
            float corr = __expf(m_i[i] - mn);
            m_i[i] = mn;
            l_i[i] *= corr;
            #pragma unroll
            for (int j = 0; j < 4; j++) acc_o[i][j] *= corr;
            float rs = 0.f;
            #pragma unroll
            for (int j = 0; j < 4; j++) {
                float p = __expf(s_acc[i][j] - mn);
                s_acc[i][j] = p;
                rs += p;
            }
            rs += __shfl_xor_sync(0xffffffffu, rs, 8);
            rs += __shfl_xor_sync(0xffffffffu, rs, 4);
            rs += __shfl_xor_sync(0xffffffffu, rs, 2);
            rs += __shfl_xor_sync(0xffffffffu, rs, 1);
            l_i[i] += rs;
        }

        __syncthreads();
        #pragma unroll
        for (int i = 0; i < 4; i++)
            #pragma unroll
            for (int j = 0; j < 4; j++) {
                int key = tx + 16*j;
                int r   = ty + 16*i;
                int rp  = (r & 48) | ((r & 15) ^ (key & 15));
                Ks[key * 64 + rp] = s_acc[i][j];
            }
        __syncthreads();

        #pragma unroll 4
        for (int kk = 0; kk < 64; kk++) {
            float a[4], bv[4];
            #pragma unroll
            for (int i = 0; i < 4; i++) {
                int r  = ty + 16*i;
                int rp = (r & 48) | ((r & 15) ^ (kk & 15));
                a[i] = Ks[kk * 64 + rp];
            }
            #pragma unroll
            for (int j = 0; j < 4; j++) bv[j] = Vs[kk * 64 + tx + 16*j];
            #pragma unroll
            for (int i = 0; i < 4; i++)
                #pragma unroll
                for (int j = 0; j < 4; j++)
                    acc_o[i][j] = fmaf(a[i], bv[j], acc_o[i][j]);
        }
    }

    float* Og = O + ((size_t)(b * S_ + qbase)) * D_ + h * HD_;
    #pragma unroll
    for (int i = 0; i < 4; i++) {
        float inv = 1.0f / l_i[i];
        #pragma unroll
        for (int j = 0; j < 4; j++)
            Og[(size_t)(ty + 16*i) * D_ + tx + 16*j] = acc_o[i][j] * inv;
    }
}

// ---------------- gelu(G)*U ----------------
__global__ void gelu_mul_kernel(const float* __restrict__ G,
                                const float* __restrict__ U,
                                float* __restrict__ Out) {
    int i = blockIdx.x * 256 + threadIdx.x;
    float4 g = ((const float4*)G)[i];
    float4 u = ((const float4*)U)[i];
    const float c0 = 0.7978845608028654f;
    const float c1 = 0.044715f;
    float4 o;
    o.x = 0.5f * g.x * (1.f + tanhf(c0 * (g.x + c1 * g.x * g.x * g.x))) * u.x;
    o.y = 0.5f * g.y * (1.f + tanhf(c0 * (g.y + c1 * g.y * g.y * g.y))) * u.y;
    o.z = 0.5f * g.z * (1.f + tanhf(c0 * (g.z + c1 * g.z * g.z * g.z))) * u.z;
    o.w = 0.5f * g.w * (1.f + tanhf(c0 * (g.w + c1 * g.w * g.w * g.w))) * u.w;
    ((float4*)Out)[i] = o;
}

// ---------------- launch ----------------
extern "C" void kernel_launch(void* const* d_in, const int* in_sizes, int n_in,
                              void* d_out, int out_size) {
    const float* x   = (const float*)d_in[0];
    const int*   sp  = (const int*)  d_in[1];
    const float* wq  = (const float*)d_in[3];
    const float* wk  = (const float*)d_in[4];
    const float* wv  = (const float*)d_in[5];
    const float* wo  = (const float*)d_in[6];
    const float* wg  = (const float*)d_in[7];
    const float* wu  = (const float*)d_in[8];
    const float* wd  = (const float*)d_in[9];
    const float* n1  = (const float*)d_in[10];
    const float* n2  = (const float*)d_in[11];
    float* out = (float*)d_out;

    float *h, *q, *k, *v, *ctx, *G, *U, *wT;
    cudaGetSymbolAddress((void**)&h,   g_h);
    cudaGetSymbolAddress((void**)&q,   g_q);
    cudaGetSymbolAddress((void**)&k,   g_k);
    cudaGetSymbolAddress((void**)&v,   g_v);
    cudaGetSymbolAddress((void**)&ctx, g_ctx);
    cudaGetSymbolAddress((void**)&G,   g_G);
    cudaGetSymbolAddress((void**)&U,   g_U);
    cudaGetSymbolAddress((void**)&wT,  g_wT);

    float* wqT = wT;
    float* wkT = wqT + (size_t)D_ * D_;
    float* wvT = wkT + (size_t)D_ * D_;
    float* woT = wvT + (size_t)D_ * D_;
    float* wgT = woT + (size_t)D_ * D_;   // [F, D]
    float* wuT = wgT + (size_t)F_ * D_;   // [F, D]
    float* wdT = wuT + (size_t)F_ * D_;   // [D, F]

    cudaFuncSetAttribute(mma_gemm<0>, cudaFuncAttributeMaxDynamicSharedMemorySize, DSMEM);
    cudaFuncSetAttribute(mma_gemm<1>, cudaFuncAttributeMaxDynamicSharedMemorySize, DSMEM);

    // weight transposes ([K,N] -> [N,K])
    dim3 tb(32, 8);
    transpose_kernel<<<dim3(D_/32, D_/32), tb>>>(wq, wqT, D_, D_);
    transpose_kernel<<<dim3(D_/32, D_/32), tb>>>(wk, wkT, D_, D_);
    transpose_kernel<<<dim3(D_/32, D_/32), tb>>>(wv, wvT, D_, D_);
    transpose_kernel<<<dim3(D_/32, D_/32), tb>>>(wo, woT, D_, D_);
    transpose_kernel<<<dim3(F_/32, D_/32), tb>>>(wg, wgT, D_, F_);
    transpose_kernel<<<dim3(F_/32, D_/32), tb>>>(wu, wuT, D_, F_);
    transpose_kernel<<<dim3(D_/32, F_/32), tb>>>(wd, wdT, F_, D_);

    // attention block
    rmsnorm_kernel<<<NT_, 256>>>(x, n1, h);
    dim3 gD(D_ / BN, NT_ / BM);
    mma_gemm<0><<<gD, 128, DSMEM>>>(h, wqT, nullptr, q, NT_, D_, D_);
    mma_gemm<0><<<gD, 128, DSMEM>>>(h, wkT, nullptr, k, NT_, D_, D_);
    mma_gemm<0><<<gD, 128, DSMEM>>>(h, wvT, nullptr, v, NT_, D_, D_);
    int ropeBlocks = NT_ * H_ * 32 / 256;
    rope_kernel<<<ropeBlocks, 256>>>(q, sp, 0.125f);
    rope_kernel<<<ropeBlocks, 256>>>(k, sp, 1.0f);
    flash_kernel<<<dim3(S_ / 64, B_ * H_), 256>>>(q, k, v, ctx);
    mma_gemm<1><<<gD, 128, DSMEM>>>(ctx, woT, x, out, NT_, D_, D_);

    // FFN block
    rmsnorm_kernel<<<NT_, 256>>>(out, n2, h);
    dim3 gF(F_ / BN, NT_ / BM);
    mma_gemm<0><<<gF, 128, DSMEM>>>(h, wgT, nullptr, G, NT_, F_, D_);
    mma_gemm<0><<<gF, 128, DSMEM>>>(h, wuT, nullptr, U, NT_, F_, D_);
    gelu_mul_kernel<<<(size_t)NT_ * F_ / 1024, 256>>>(G, U, G);
    mma_gemm<1><<<gD, 128, DSMEM>>>(G, wdT, out, out, NT_, D_, F_);
}

// round 5
// speedup vs baseline: 5.6573x; 1.3706x over previous
#include <cuda_runtime.h>
#include <math.h>
#include <stdint.h>

#define B_  4
#define S_  2048
#define D_  1024
#define H_  16
#define HD_ 64
#define F_  4096
#define NT_ (B_*S_)   // 8192 tokens

// ---------------- scratch (no allocation allowed) ----------------
__device__ float g_h  [(size_t)NT_*D_];
__device__ float g_q  [(size_t)NT_*D_];
__device__ float g_k  [(size_t)NT_*D_];
__device__ float g_v  [(size_t)NT_*D_];
__device__ float g_ctx[(size_t)NT_*D_];
__device__ float g_G  [(size_t)NT_*F_];
__device__ float g_U  [(size_t)NT_*F_];
__device__ float g_wT [(size_t)4*D_*D_ + (size_t)3*D_*F_];

// ---------------- helpers ----------------
__device__ __forceinline__ uint32_t sm_u32(const void* p) {
    uint32_t a;
    asm("{ .reg .u64 t; cvta.to.shared.u64 t, %1; cvt.u32.u64 %0, t; }" : "=r"(a) : "l"(p));
    return a;
}
__device__ __forceinline__ float rna(float x) {
    uint32_t u;
    asm("cvt.rna.tf32.f32 %0, %1;" : "=r"(u) : "f"(x));
    return __uint_as_float(u);
}
__device__ __forceinline__ void cp16(uint32_t dst, const void* src) {
    asm volatile("cp.async.cg.shared.global [%0], [%1], 16;" :: "r"(dst), "l"(src));
}
__device__ __forceinline__ void cp_commit() {
    asm volatile("cp.async.commit_group;" ::: "memory");
}
template<int N> __device__ __forceinline__ void cp_wait() {
    asm volatile("cp.async.wait_group %0;" :: "n"(N) : "memory");
}
__device__ __forceinline__ void ldm_x4(uint32_t& r0, uint32_t& r1, uint32_t& r2,
                                       uint32_t& r3, uint32_t addr) {
    asm volatile("ldmatrix.sync.aligned.m8n8.x4.shared.b16 {%0,%1,%2,%3}, [%4];"
                 : "=r"(r0), "=r"(r1), "=r"(r2), "=r"(r3) : "r"(addr));
}
__device__ __forceinline__ void mma_tf32(float* c, const uint32_t* a, const uint32_t* b) {
    asm volatile(
        "mma.sync.aligned.m16n8k8.row.col.f32.tf32.tf32.f32 "
        "{%0,%1,%2,%3}, {%4,%5,%6,%7}, {%8,%9}, {%0,%1,%2,%3};"
        : "+f"(c[0]), "+f"(c[1]), "+f"(c[2]), "+f"(c[3])
        : "r"(a[0]), "r"(a[1]), "r"(a[2]), "r"(a[3]), "r"(b[0]), "r"(b[1]));
}

// ---------------- TF32 mma.sync GEMM (unchanged from R4) ----------------
#define BM 128
#define BN 128
#define BK 32
#define STAGES 3
#define ASTG (BM*BK*4)
#define SSTG (2*ASTG)
#define DSMEM (STAGES*SSTG)

template<int ADD_RES>
__global__ __launch_bounds__(128, 2)
void mma_gemm(const float* __restrict__ A, const float* __restrict__ Bt,
              const float* __restrict__ Res, float* __restrict__ C,
              int M, int N, int K) {
    extern __shared__ float smem[];
    const uint32_t sb = sm_u32(smem);
    const int tid  = threadIdx.x;
    const int lane = tid & 31;
    const int wid  = tid >> 5;
    const int wm   = wid >> 1;
    const int wn   = wid & 1;
    const int m0   = blockIdx.y * BM;
    const int n0   = blockIdx.x * BN;

    const int lrow = tid >> 3;
    const int lc   = tid & 7;
    const uint32_t dA0 = (uint32_t)lrow * 128 + (uint32_t)((lc ^ (lrow & 7)) << 4);
    const float* pA = A  + (size_t)(m0 + lrow) * K + lc * 4;
    const float* pB = Bt + (size_t)(n0 + lrow) * K + lc * 4;

    const int q  = lane >> 3;
    const int r8 = lane & 7;
    const int qh = q >> 1;
    const int ql = q & 1;
    uint32_t aRow[4], bRow[4];
    int am7[4], bn7[4];
    #pragma unroll
    for (int f = 0; f < 4; f++) {
        int m = wm * 64 + f * 16 + ql * 8 + r8;
        aRow[f] = (uint32_t)m * 128;
        am7[f]  = m & 7;
        int n = wn * 64 + f * 16 + ql * 8 + r8;
        bRow[f] = ASTG + (uint32_t)n * 128;
        bn7[f]  = n & 7;
    }

    float acc[4][8][4];
    #pragma unroll
    for (int i = 0; i < 4; i++)
        #pragma unroll
        for (int j = 0; j < 8; j++)
            #pragma unroll
            for (int c = 0; c < 4; c++) acc[i][j][c] = 0.f;

    const int nt = K / BK;
    const size_t stepA = (size_t)16 * K;

    #define LOAD_TILE(stg, kt) do {                                           \
        uint32_t base = sb + (uint32_t)(stg) * SSTG;                          \
        size_t kk = (size_t)(kt) * BK;                                        \
        _Pragma("unroll")                                                     \
        for (int i = 0; i < 8; i++)                                           \
            cp16(base + dA0 + 2048u * i, pA + stepA * i + kk);                \
        _Pragma("unroll")                                                     \
        for (int i = 0; i < 8; i++)                                           \
            cp16(base + ASTG + dA0 + 2048u * i, pB + stepA * i + kk);         \
    } while (0)

    LOAD_TILE(0, 0); cp_commit();
    LOAD_TILE(1, 1); cp_commit();

    uint32_t a2[2][4][4], b2[2][8][2];

    #define LOAD_FRAGS(SB, s, buf) do {                                       \
        _Pragma("unroll")                                                     \
        for (int f = 0; f < 4; f++) {                                         \
            uint32_t ad = (SB) + aRow[f] + (uint32_t)(((2*(s)+qh) ^ am7[f]) << 4); \
            ldm_x4(a2[buf][f][0], a2[buf][f][1], a2[buf][f][2], a2[buf][f][3], ad); \
        }                                                                     \
        _Pragma("unroll")                                                     \
        for (int f = 0; f < 4; f++) {                                         \
            uint32_t bd = (SB) + bRow[f] + (uint32_t)(((2*(s)+qh) ^ bn7[f]) << 4); \
            ldm_x4(b2[buf][2*f][0], b2[buf][2*f+1][0],                        \
                   b2[buf][2*f][1], b2[buf][2*f+1][1], bd);                   \
        }                                                                     \
    } while (0)

    int stage = 0;
    for (int kt = 0; kt < nt; kt++) {
        cp_wait<1>();
        __syncthreads();
        int lk = kt + 2;
        if (lk < nt) {
            int lst = stage + 2; if (lst >= STAGES) lst -= STAGES;
            LOAD_TILE(lst, lk);
        }
        cp_commit();

        const uint32_t SB = sb + (uint32_t)stage * SSTG;
        LOAD_FRAGS(SB, 0, 0);
        #pragma unroll
        for (int s = 0; s < 4; s++) {
            if (s < 3) LOAD_FRAGS(SB, s + 1, (s + 1) & 1);
            int cur = s & 1;
            #pragma unroll
            for (int mf = 0; mf < 4; mf++)
                #pragma unroll
                for (int nf = 0; nf < 8; nf++)
                    mma_tf32(acc[mf][nf], a2[cur][mf], b2[cur][nf]);
        }
        if (++stage == STAGES) stage = 0;
    }
    #undef LOAD_FRAGS
    #undef LOAD_TILE

    const int g  = lane >> 2;
    const int tg = lane & 3;
    #pragma unroll
    for (int mf = 0; mf < 4; mf++) {
        int row = m0 + wm * 64 + mf * 16 + g;
        #pragma unroll
        for (int nf = 0; nf < 8; nf++) {
            int col = n0 + wn * 64 + nf * 8 + tg * 2;
            float2 v0 = {acc[mf][nf][0], acc[mf][nf][1]};
            float2 v1 = {acc[mf][nf][2], acc[mf][nf][3]};
            float* c0 = C + (size_t)row * N + col;
            float* c1 = C + (size_t)(row + 8) * N + col;
            if (ADD_RES) {
                float2 r0 = *(const float2*)(Res + (size_t)row * N + col);
                float2 r1 = *(const float2*)(Res + (size_t)(row + 8) * N + col);
                v0.x += r0.x; v0.y += r0.y;
                v1.x += r1.x; v1.y += r1.y;
            }
            *(float2*)c0 = v0;
            *(float2*)c1 = v1;
        }
    }
}

// ---------------- transpose + rna round: in[R][C] -> out[C][R] ----------------
__global__ void transpose_kernel(const float* __restrict__ in,
                                 float* __restrict__ out, int R, int C) {
    __shared__ float t[32][33];
    int bx = blockIdx.x * 32, by = blockIdx.y * 32;
    int x = bx + threadIdx.x;
    #pragma unroll
    for (int i = 0; i < 32; i += 8)
        t[threadIdx.y + i][threadIdx.x] = in[(size_t)(by + threadIdx.y + i) * C + x];
    __syncthreads();
    int xo = by + threadIdx.x;
    #pragma unroll
    for (int i = 0; i < 32; i += 8)
        out[(size_t)(bx + threadIdx.y + i) * R + xo] = rna(t[threadIdx.x][threadIdx.y + i]);
}

// ---------------- RMSNorm (rna-rounded output; feeds GEMMs only) ----------------
__global__ void rmsnorm_kernel(const float* __restrict__ x,
                               const float* __restrict__ scale,
                               float* __restrict__ out) {
    int row = blockIdx.x;
    int t = threadIdx.x;
    const float4* xr = (const float4*)(x + (size_t)row * D_);
    float4 v = xr[t];
    float ss = v.x*v.x + v.y*v.y + v.z*v.z + v.w*v.w;
    #pragma unroll
    for (int o = 16; o; o >>= 1) ss += __shfl_xor_sync(0xffffffffu, ss, o);
    __shared__ float red[8];
    if ((t & 31) == 0) red[t >> 5] = ss;
    __syncthreads();
    if (t < 8) {
        float s2 = red[t];
        s2 += __shfl_xor_sync(0xffu, s2, 4);
        s2 += __shfl_xor_sync(0xffu, s2, 2);
        s2 += __shfl_xor_sync(0xffu, s2, 1);
        if (t == 0) red[0] = s2;
    }
    __syncthreads();
    float inv = rsqrtf(red[0] * (1.0f / D_) + 1e-6f);
    float4 s4 = ((const float4*)scale)[t];
    float4 o4;
    o4.x = rna(v.x * inv * s4.x);
    o4.y = rna(v.y * inv * s4.y);
    o4.z = rna(v.z * inv * s4.z);
    o4.w = rna(v.w * inv * s4.w);
    ((float4*)(out + (size_t)row * D_))[t] = o4;
}

// ---------------- RoPE (rna-rounded; feeds flash mma) ----------------
__global__ void rope_kernel(float* __restrict__ qk,
                            const int* __restrict__ pos, float scale) {
    int idx = blockIdx.x * 256 + threadIdx.x;
    int i = idx & 31;
    int h = (idx >> 5) & (H_ - 1);
    int t = idx >> 9;
    float p = (float)pos[t];
    float frac = (float)(2 * i) / (float)HD_;
    float ts = powf(10000.0f, frac);
    float ang = p / ts;
    float sn, cs;
    sincosf(ang, &sn, &cs);
    float* base = qk + (size_t)t * D_ + h * HD_;
    float x1 = base[i], x2 = base[i + 32];
    base[i]      = rna((x1 * cs - x2 * sn) * scale);
    base[i + 32] = rna((x2 * cs + x1 * sn) * scale);
}

// ---------------- causal flash attention (tf32 mma.sync) ----------------
// block: 128 q-rows x 64 kv, 4 warps (32 q-rows each).
// smem: Qs[128][64], Ks[64][64], Vt[64][64] (transposed), Ps[128][64]; all
// XOR-swizzled 256B rows (16 chunks of 16B, sw = (c&8)|((c&7)^(r&7))).
#define FSMEM ((128*64 + 64*64 + 64*64 + 128*64) * 4)   // 98304 B

__global__ __launch_bounds__(128)
void flash_mma(const float* __restrict__ Q, const float* __restrict__ K,
               const float* __restrict__ V, float* __restrict__ O) {
    extern __shared__ float fsm[];
    float* Qs = fsm;            // 8192 floats
    float* Ks = fsm + 8192;     // 4096
    float* Vt = fsm + 12288;    // 4096
    float* Ps = fsm + 16384;    // 8192
    const uint32_t QSa = sm_u32(Qs), KSa = sm_u32(Ks),
                   VTa = sm_u32(Vt), PSa = sm_u32(Ps);

    const int qt = gridDim.x - 1 - blockIdx.x;   // big tiles first
    const int bh = blockIdx.y;
    const int b = bh >> 4, h = bh & 15;
    const int tid = threadIdx.x, lane = tid & 31, warp = tid >> 5;
    const int qbase = qt * 128;
    const int wq = warp * 32;

    // load Q tile (128x64)
    const float* Qg = Q + ((size_t)(b * S_ + qbase)) * D_ + h * HD_;
    #pragma unroll
    for (int i = 0; i < 16; i++) {
        int ch = tid + 128 * i;
        int r = ch >> 4, c = ch & 15;
        uint32_t sw = (c & 8) | ((c & 7) ^ (r & 7));
        *(float4*)(Qs + r * 64 + sw * 4) = *(const float4*)(Qg + (size_t)r * D_ + c * 4);
    }

    const int q4 = lane >> 3, r8 = lane & 7;
    const int qh = q4 >> 1, ql = q4 & 1;
    int aR[2], bR[4];
    #pragma unroll
    for (int mf = 0; mf < 2; mf++) aR[mf] = wq + mf * 16 + ql * 8 + r8;
    #pragma unroll
    for (int f2 = 0; f2 < 4; f2++) bR[f2] = f2 * 16 + ql * 8 + r8;

    float m_i[2][2], l_i[2][2], acc[2][8][4];
    #pragma unroll
    for (int mf = 0; mf < 2; mf++) {
        m_i[mf][0] = m_i[mf][1] = -3.0e38f;
        l_i[mf][0] = l_i[mf][1] = 0.f;
        #pragma unroll
        for (int nf = 0; nf < 8; nf++)
            #pragma unroll
            for (int c = 0; c < 4; c++) acc[mf][nf][c] = 0.f;
    }

    const int rlo = lane >> 2;        // row within 16-frag (c0,c1); +8 for c2,c3
    const int cq  = (lane & 3) * 2;   // col pair base

    const int jmax = 2 * qt + 1;
    for (int jt = 0; jt <= jmax; jt++) {
        const int kbase = jt * 64;
        __syncthreads();     // prior tile's Ks/Vt reads complete
        const float* Kg = K + ((size_t)(b * S_ + kbase)) * D_ + h * HD_;
        const float* Vg = V + ((size_t)(b * S_ + kbase)) * D_ + h * HD_;
        #pragma unroll
        for (int i = 0; i < 8; i++) {
            int ch = tid + 128 * i;
            int r = ch >> 4, c = ch & 15;
            uint32_t sw = (c & 8) | ((c & 7) ^ (r & 7));
            *(float4*)(Ks + r * 64 + sw * 4) = *(const float4*)(Kg + (size_t)r * D_ + c * 4);
            float4 vv = *(const float4*)(Vg + (size_t)r * D_ + c * 4);
            int d4 = c * 4, kk = r;
            int kc = kk >> 2, km = kk & 3;
            #pragma unroll
            for (int j = 0; j < 4; j++) {
                int d = d4 + j;
                uint32_t swv = (uint32_t)((kc & 8) | ((kc & 7) ^ (d & 7)));
                Vt[d * 64 + swv * 4 + km] = rna(j == 0 ? vv.x : j == 1 ? vv.y : j == 2 ? vv.z : vv.w);
            }
        }
        __syncthreads();

        // ---- S = Q K^T ----
        float sa[2][8][4];
        #pragma unroll
        for (int mf = 0; mf < 2; mf++)
            #pragma unroll
            for (int nf = 0; nf < 8; nf++)
                #pragma unroll
                for (int c = 0; c < 4; c++) sa[mf][nf][c] = 0.f;

        #pragma unroll
        for (int s = 0; s < 8; s++) {
            uint32_t af[2][4], bf[8][2];
            #pragma unroll
            for (int mf = 0; mf < 2; mf++) {
                uint32_t sw = (uint32_t)((((2*s+qh) & 8)) | (((2*s+qh) & 7) ^ (aR[mf] & 7)));
                ldm_x4(af[mf][0], af[mf][1], af[mf][2], af[mf][3],
                       QSa + (uint32_t)aR[mf] * 256 + sw * 16);
            }
            #pragma unroll
            for (int f2 = 0; f2 < 4; f2++) {
                uint32_t sw = (uint32_t)((((2*s+qh) & 8)) | (((2*s+qh) & 7) ^ (bR[f2] & 7)));
                ldm_x4(bf[2*f2][0], bf[2*f2+1][0], bf[2*f2][1], bf[2*f2+1][1],
                       KSa + (uint32_t)bR[f2] * 256 + sw * 16);
            }
            #pragma unroll
            for (int mf = 0; mf < 2; mf++)
                #pragma unroll
                for (int nf = 0; nf < 8; nf++)
                    mma_tf32(sa[mf][nf], af[mf], bf[nf]);
        }

        // ---- causal mask (last two tiles only) ----
        if (jt >= 2 * qt) {
            #pragma unroll
            for (int mf = 0; mf < 2; mf++) {
                int q0 = qbase + wq + mf * 16 + rlo;
                #pragma unroll
                for (int nf = 0; nf < 8; nf++) {
                    int k0 = kbase + nf * 8 + cq;
                    if (k0     > q0    ) sa[mf][nf][0] = -1.0e30f;
                    if (k0 + 1 > q0    ) sa[mf][nf][1] = -1.0e30f;
                    if (k0     > q0 + 8) sa[mf][nf][2] = -1.0e30f;
                    if (k0 + 1 > q0 + 8) sa[mf][nf][3] = -1.0e30f;
                }
            }
        }

        // ---- online softmax ----
        #pragma unroll
        for (int mf = 0; mf < 2; mf++) {
            float mx0 = -3.0e38f, mx1 = -3.0e38f;
            #pragma unroll
            for (int nf = 0; nf < 8; nf++) {
                mx0 = fmaxf(mx0, fmaxf(sa[mf][nf][0], sa[mf][nf][1]));
                mx1 = fmaxf(mx1, fmaxf(sa[mf][nf][2], sa[mf][nf][3]));
            }
            mx0 = fmaxf(mx0, __shfl_xor_sync(0xffffffffu, mx0, 1));
            mx0 = fmaxf(mx0, __shfl_xor_sync(0xffffffffu, mx0, 2));
            mx1 = fmaxf(mx1, __shfl_xor_sync(0xffffffffu, mx1, 1));
            mx1 = fmaxf(mx1, __shfl_xor_sync(0xffffffffu, mx1, 2));
            float mn0 = fmaxf(m_i[mf][0], mx0);
            float mn1 = fmaxf(m_i[mf][1], mx1);
            float cr0 = __expf(m_i[mf][0] - mn0);
            float cr1 = __expf(m_i[mf][1] - mn1);
            m_i[mf][0] = mn0; m_i[mf][1] = mn1;

            int row0 = wq + mf * 16 + rlo;
            int row1 = row0 + 8;
            float rs0 = 0.f, rs1 = 0.f;
            #pragma unroll
            for (int nf = 0; nf < 8; nf++) {
                float p0 = rna(__expf(sa[mf][nf][0] - mn0));
                float p1 = rna(__expf(sa[mf][nf][1] - mn0));
                float p2 = rna(__expf(sa[mf][nf][2] - mn1));
                float p3 = rna(__expf(sa[mf][nf][3] - mn1));
                rs0 += p0 + p1;
                rs1 += p2 + p3;
                int colc = nf * 2 + ((lane & 3) >> 1);
                int cmod = ((lane & 3) & 1) * 2;
                uint32_t sw0 = (uint32_t)((colc & 8) | ((colc & 7) ^ (row0 & 7)));
                uint32_t sw1 = (uint32_t)((colc & 8) | ((colc & 7) ^ (row1 & 7)));
                *(float2*)(Ps + row0 * 64 + sw0 * 4 + cmod) = make_float2(p0, p1);
                *(float2*)(Ps + row1 * 64 + sw1 * 4 + cmod) = make_float2(p2, p3);
            }
            rs0 += __shfl_xor_sync(0xffffffffu, rs0, 1);
            rs0 += __shfl_xor_sync(0xffffffffu, rs0, 2);
            rs1 += __shfl_xor_sync(0xffffffffu, rs1, 1);
            rs1 += __shfl_xor_sync(0xffffffffu, rs1, 2);
            l_i[mf][0] = l_i[mf][0] * cr0 + rs0;
            l_i[mf][1] = l_i[mf][1] * cr1 + rs1;
            #pragma unroll
            for (int nf = 0; nf < 8; nf++) {
                acc[mf][nf][0] *= cr0; acc[mf][nf][1] *= cr0;
                acc[mf][nf][2] *= cr1; acc[mf][nf][3] *= cr1;
            }
        }
        __syncwarp();

        // ---- O += P V ----
        #pragma unroll
        for (int s = 0; s < 8; s++) {
            uint32_t af[2][4], bf[8][2];
            #pragma unroll
            for (int mf = 0; mf < 2; mf++) {
                uint32_t sw = (uint32_t)((((2*s+qh) & 8)) | (((2*s+qh) & 7) ^ (aR[mf] & 7)));
                ldm_x4(af[mf][0], af[mf][1], af[mf][2], af[mf][3],
                       PSa + (uint32_t)aR[mf] * 256 + sw * 16);
            }
            #pragma unroll
            for (int f2 = 0; f2 < 4; f2++) {
                uint32_t sw = (uint32_t)((((2*s+qh) & 8)) | (((2*s+qh) & 7) ^ (bR[f2] & 7)));
                ldm_x4(bf[2*f2][0], bf[2*f2+1][0], bf[2*f2][1], bf[2*f2+1][1],
                       VTa + (uint32_t)bR[f2] * 256 + sw * 16);
            }
            #pragma unroll
            for (int mf = 0; mf < 2; mf++)
                #pragma unroll
                for (int nf = 0; nf < 8; nf++)
                    mma_tf32(acc[mf][nf], af[mf], bf[nf]);
        }
    }

    // ---- write O (rounded: feeds o-proj GEMM) ----
    #pragma unroll
    for (int mf = 0; mf < 2; mf++) {
        float inv0 = 1.0f / l_i[mf][0];
        float inv1 = 1.0f / l_i[mf][1];
        int row0 = qbase + wq + mf * 16 + rlo;
        float* O0 = O + ((size_t)(b * S_ + row0)) * D_ + h * HD_;
        float* O1 = O + ((size_t)(b * S_ + row0 + 8)) * D_ + h * HD_;
        #pragma unroll
        for (int nf = 0; nf < 8; nf++) {
            int col = nf * 8 + cq;
            *(float2*)(O0 + col) = make_float2(rna(acc[mf][nf][0] * inv0),
                                               rna(acc[mf][nf][1] * inv0));
            *(float2*)(O1 + col) = make_float2(rna(acc[mf][nf][2] * inv1),
                                               rna(acc[mf][nf][3] * inv1));
        }
    }
}

// ---------------- gelu(G)*U (rna-rounded; feeds down GEMM) ----------------
__global__ void gelu_mul_kernel(const float* __restrict__ G,
                                const float* __restrict__ U,
                                float* __restrict__ Out) {
    int i = blockIdx.x * 256 + threadIdx.x;
    float4 g = ((const float4*)G)[i];
    float4 u = ((const float4*)U)[i];
    const float c0 = 0.7978845608028654f;
    const float c1 = 0.044715f;
    float4 o;
    o.x = rna(0.5f * g.x * (1.f + tanhf(c0 * (g.x + c1 * g.x * g.x * g.x))) * u.x);
    o.y = rna(0.5f * g.y * (1.f + tanhf(c0 * (g.y + c1 * g.y * g.y * g.y))) * u.y);
    o.z = rna(0.5f * g.z * (1.f + tanhf(c0 * (g.z + c1 * g.z * g.z * g.z))) * u.z);
    o.w = rna(0.5f * g.w * (1.f + tanhf(c0 * (g.w + c1 * g.w * g.w * g.w))) * u.w);
    ((float4*)Out)[i] = o;
}

// ---------------- launch ----------------
extern "C" void kernel_launch(void* const* d_in, const int* in_sizes, int n_in,
                              void* d_out, int out_size) {
    const float* x   = (const float*)d_in[0];
    const int*   sp  = (const int*)  d_in[1];
    const float* wq  = (const float*)d_in[3];
    const float* wk  = (const float*)d_in[4];
    const float* wv  = (const float*)d_in[5];
    const float* wo  = (const float*)d_in[6];
    const float* wg  = (const float*)d_in[7];
    const float* wu  = (const float*)d_in[8];
    const float* wd  = (const float*)d_in[9];
    const float* n1  = (const float*)d_in[10];
    const float* n2  = (const float*)d_in[11];
    float* out = (float*)d_out;

    float *h, *q, *k, *v, *ctx, *G, *U, *wT;
    cudaGetSymbolAddress((void**)&h,   g_h);
    cudaGetSymbolAddress((void**)&q,   g_q);
    cudaGetSymbolAddress((void**)&k,   g_k);
    cudaGetSymbolAddress((void**)&v,   g_v);
    cudaGetSymbolAddress((void**)&ctx, g_ctx);
    cudaGetSymbolAddress((void**)&G,   g_G);
    cudaGetSymbolAddress((void**)&U,   g_U);
    cudaGetSymbolAddress((void**)&wT,  g_wT);

    float* wqT = wT;
    float* wkT = wqT + (size_t)D_ * D_;
    float* wvT = wkT + (size_t)D_ * D_;
    float* woT = wvT + (size_t)D_ * D_;
    float* wgT = woT + (size_t)D_ * D_;
    float* wuT = wgT + (size_t)F_ * D_;
    float* wdT = wuT + (size_t)F_ * D_;

    cudaFuncSetAttribute(mma_gemm<0>, cudaFuncAttributeMaxDynamicSharedMemorySize, DSMEM);
    cudaFuncSetAttribute(mma_gemm<1>, cudaFuncAttributeMaxDynamicSharedMemorySize, DSMEM);
    cudaFuncSetAttribute(flash_mma,   cudaFuncAttributeMaxDynamicSharedMemorySize, FSMEM);

    dim3 tb(32, 8);
    transpose_kernel<<<dim3(D_/32, D_/32), tb>>>(wq, wqT, D_, D_);
    transpose_kernel<<<dim3(D_/32, D_/32), tb>>>(wk, wkT, D_, D_);
    transpose_kernel<<<dim3(D_/32, D_/32), tb>>>(wv, wvT, D_, D_);
    transpose_kernel<<<dim3(D_/32, D_/32), tb>>>(wo, woT, D_, D_);
    transpose_kernel<<<dim3(F_/32, D_/32), tb>>>(wg, wgT, D_, F_);
    transpose_kernel<<<dim3(F_/32, D_/32), tb>>>(wu, wuT, D_, F_);
    transpose_kernel<<<dim3(D_/32, F_/32), tb>>>(wd, wdT, F_, D_);

    // attention block
    rmsnorm_kernel<<<NT_, 256>>>(x, n1, h);
    dim3 gD(D_ / BN, NT_ / BM);
    mma_gemm<0><<<gD, 128, DSMEM>>>(h, wqT, nullptr, q, NT_, D_, D_);
    mma_gemm<0><<<gD, 128, DSMEM>>>(h, wkT, nullptr, k, NT_, D_, D_);
    mma_gemm<0><<<gD, 128, DSMEM>>>(h, wvT, nullptr, v, NT_, D_, D_);
    int ropeBlocks = NT_ * H_ * 32 / 256;
    rope_kernel<<<ropeBlocks, 256>>>(q, sp, 0.125f);
    rope_kernel<<<ropeBlocks, 256>>>(k, sp, 1.0f);
    flash_mma<<<dim3(S_ / 128, B_ * H_), 128, FSMEM>>>(q, k, v, ctx);
    mma_gemm<1><<<gD, 128, DSMEM>>>(ctx, woT, x, out, NT_, D_, D_);

    // FFN block
    rmsnorm_kernel<<<NT_, 256>>>(out, n2, h);
    dim3 gF(F_ / BN, NT_ / BM);
    mma_gemm<0><<<gF, 128, DSMEM>>>(h, wgT, nullptr, G, NT_, F_, D_);
    mma_gemm<0><<<gF, 128, DSMEM>>>(h, wuT, nullptr, U, NT_, F_, D_);
    gelu_mul_kernel<<<(size_t)NT_ * F_ / 1024, 256>>>(G, U, G);
    mma_gemm<1><<<gD, 128, DSMEM>>>(G, wdT, out, out, NT_, D_, F_);
}

// round 6
// speedup vs baseline: 5.8970x; 1.0424x over previous
#include <cuda_runtime.h>
#include <math.h>
#include <stdint.h>

#define B_  4
#define S_  2048
#define D_  1024
#define H_  16
#define HD_ 64
#define F_  4096
#define NT_ (B_*S_)   // 8192 tokens
#define SD_ (3*D_)    // fused qkv row stride

// ---------------- scratch (no allocation allowed) ----------------
__device__ float g_h  [(size_t)NT_*D_];
__device__ float g_qkv[(size_t)NT_*SD_];
__device__ float g_ctx[(size_t)NT_*D_];
__device__ float g_GU [(size_t)NT_*2*F_];
__device__ float g_G  [(size_t)NT_*F_];
__device__ float g_wT [(size_t)4*D_*D_ + (size_t)3*D_*F_];

// ---------------- helpers ----------------
__device__ __forceinline__ uint32_t sm_u32(const void* p) {
    uint32_t a;
    asm("{ .reg .u64 t; cvta.to.shared.u64 t, %1; cvt.u32.u64 %0, t; }" : "=r"(a) : "l"(p));
    return a;
}
__device__ __forceinline__ float rna(float x) {
    uint32_t u;
    asm("cvt.rna.tf32.f32 %0, %1;" : "=r"(u) : "f"(x));
    return __uint_as_float(u);
}
__device__ __forceinline__ void cp16(uint32_t dst, const void* src) {
    asm volatile("cp.async.cg.shared.global [%0], [%1], 16;" :: "r"(dst), "l"(src));
}
__device__ __forceinline__ void cp_commit() {
    asm volatile("cp.async.commit_group;" ::: "memory");
}
template<int N> __device__ __forceinline__ void cp_wait() {
    asm volatile("cp.async.wait_group %0;" :: "n"(N) : "memory");
}
__device__ __forceinline__ void ldm_x4(uint32_t& r0, uint32_t& r1, uint32_t& r2,
                                       uint32_t& r3, uint32_t addr) {
    asm volatile("ldmatrix.sync.aligned.m8n8.x4.shared.b16 {%0,%1,%2,%3}, [%4];"
                 : "=r"(r0), "=r"(r1), "=r"(r2), "=r"(r3) : "r"(addr));
}
__device__ __forceinline__ void mma_tf32(float* c, const uint32_t* a, const uint32_t* b) {
    asm volatile(
        "mma.sync.aligned.m16n8k8.row.col.f32.tf32.tf32.f32 "
        "{%0,%1,%2,%3}, {%4,%5,%6,%7}, {%8,%9}, {%0,%1,%2,%3};"
        : "+f"(c[0]), "+f"(c[1]), "+f"(c[2]), "+f"(c[3])
        : "r"(a[0]), "r"(a[1]), "r"(a[2]), "r"(a[3]), "r"(b[0]), "r"(b[1]));
}

// ---------------- TF32 mma.sync GEMM: 256 thr, 8 warps, warp tile 64x32 ----------------
#define BM 128
#define BN 128
#define BK 32
#define STAGES 3
#define ASTG (BM*BK*4)     // 16384 B
#define SSTG (2*ASTG)      // 32768 B
#define DSMEM (STAGES*SSTG)

template<int ADD_RES>
__global__ __launch_bounds__(256, 2)
void mma_gemm(const float* __restrict__ A, const float* __restrict__ Bt,
              const float* __restrict__ Res, float* __restrict__ C,
              int M, int N, int K) {
    extern __shared__ float smem[];
    const uint32_t sb = sm_u32(smem);
    const int tid  = threadIdx.x;
    const int lane = tid & 31;
    const int wid  = tid >> 5;        // 0..7
    const int wm   = wid >> 2;        // 0..1 (64-row halves)
    const int wn   = wid & 3;         // 0..3 (32-col quarters)
    const int m0   = blockIdx.y * BM;
    const int n0   = blockIdx.x * BN;

    // cp.async mapping: 256 threads, 4 chunks each per tile (rows stride 32)
    const int lrow = tid >> 3;        // 0..31
    const int lc   = tid & 7;
    const uint32_t dA0 = (uint32_t)lrow * 128 + (uint32_t)((lc ^ (lrow & 7)) << 4);
    const float* pA = A  + (size_t)(m0 + lrow) * K + lc * 4;
    const float* pB = Bt + (size_t)(n0 + lrow) * K + lc * 4;

    // ldmatrix addresses
    const int q4 = lane >> 3, r8 = lane & 7;
    const int qh = q4 >> 1, ql = q4 & 1;
    uint32_t aRow[4]; int am7[4];
    #pragma unroll
    for (int mf = 0; mf < 4; mf++) {
        int m = wm * 64 + mf * 16 + ql * 8 + r8;
        aRow[mf] = (uint32_t)m * 128;
        am7[mf]  = m & 7;
    }
    uint32_t bRow[2]; int bn7[2];
    #pragma unroll
    for (int f2 = 0; f2 < 2; f2++) {
        int n = wn * 32 + f2 * 16 + ql * 8 + r8;
        bRow[f2] = ASTG + (uint32_t)n * 128;
        bn7[f2]  = n & 7;
    }

    float acc[4][4][4];
    #pragma unroll
    for (int i = 0; i < 4; i++)
        #pragma unroll
        for (int j = 0; j < 4; j++)
            #pragma unroll
            for (int c = 0; c < 4; c++) acc[i][j][c] = 0.f;

    const int nt = K / BK;
    const size_t stepA = (size_t)32 * K;

    #define LOAD_TILE(stg, kt) do {                                           \
        uint32_t base = sb + (uint32_t)(stg) * SSTG;                          \
        size_t kk = (size_t)(kt) * BK;                                        \
        _Pragma("unroll")                                                     \
        for (int i = 0; i < 4; i++)                                           \
            cp16(base + dA0 + 4096u * i, pA + stepA * i + kk);                \
        _Pragma("unroll")                                                     \
        for (int i = 0; i < 4; i++)                                           \
            cp16(base + ASTG + dA0 + 4096u * i, pB + stepA * i + kk);         \
    } while (0)

    LOAD_TILE(0, 0); cp_commit();
    LOAD_TILE(1, 1); cp_commit();

    int stage = 0;
    for (int kt = 0; kt < nt; kt++) {
        cp_wait<1>();
        __syncthreads();
        int lk = kt + 2;
        if (lk < nt) {
            int lst = stage + 2; if (lst >= STAGES) lst -= STAGES;
            LOAD_TILE(lst, lk);
        }
        cp_commit();

        const uint32_t SB = sb + (uint32_t)stage * SSTG;
        #pragma unroll
        for (int s = 0; s < 4; s++) {
            uint32_t af[4][4], bf[4][2];
            #pragma unroll
            for (int mf = 0; mf < 4; mf++) {
                uint32_t ad = SB + aRow[mf] + (uint32_t)(((2*s+qh) ^ am7[mf]) << 4);
                ldm_x4(af[mf][0], af[mf][1], af[mf][2], af[mf][3], ad);
            }
            #pragma unroll
            for (int f2 = 0; f2 < 2; f2++) {
                uint32_t bd = SB + bRow[f2] + (uint32_t)(((2*s+qh) ^ bn7[f2]) << 4);
                ldm_x4(bf[2*f2][0], bf[2*f2+1][0], bf[2*f2][1], bf[2*f2+1][1], bd);
            }
            #pragma unroll
            for (int mf = 0; mf < 4; mf++)
                #pragma unroll
                for (int nf = 0; nf < 4; nf++)
                    mma_tf32(acc[mf][nf], af[mf], bf[nf]);
        }
        if (++stage == STAGES) stage = 0;
    }
    #undef LOAD_TILE

    const int g  = lane >> 2;
    const int tg = lane & 3;
    #pragma unroll
    for (int mf = 0; mf < 4; mf++) {
        int row = m0 + wm * 64 + mf * 16 + g;
        #pragma unroll
        for (int nf = 0; nf < 4; nf++) {
            int col = n0 + wn * 32 + nf * 8 + tg * 2;
            float2 v0 = {acc[mf][nf][0], acc[mf][nf][1]};
            float2 v1 = {acc[mf][nf][2], acc[mf][nf][3]};
            float* c0 = C + (size_t)row * N + col;
            float* c1 = C + (size_t)(row + 8) * N + col;
            if (ADD_RES) {
                float2 r0 = *(const float2*)(Res + (size_t)row * N + col);
                float2 r1 = *(const float2*)(Res + (size_t)(row + 8) * N + col);
                v0.x += r0.x; v0.y += r0.y;
                v1.x += r1.x; v1.y += r1.y;
            }
            *(float2*)c0 = v0;
            *(float2*)c1 = v1;
        }
    }
}

// ---------------- batched transpose + rna: in_z[R][C] -> out_z[C][R] ----------------
__global__ void transposeN_kernel(const float* __restrict__ i0, const float* __restrict__ i1,
                                  const float* __restrict__ i2, const float* __restrict__ i3,
                                  float* __restrict__ out, int R, int C) {
    __shared__ float t[32][33];
    const float* in = blockIdx.z == 0 ? i0 : blockIdx.z == 1 ? i1
                    : blockIdx.z == 2 ? i2 : i3;
    float* o = out + (size_t)blockIdx.z * R * C;
    int bx = blockIdx.x * 32, by = blockIdx.y * 32;
    int x = bx + threadIdx.x;
    #pragma unroll
    for (int i = 0; i < 32; i += 8)
        t[threadIdx.y + i][threadIdx.x] = in[(size_t)(by + threadIdx.y + i) * C + x];
    __syncthreads();
    int xo = by + threadIdx.x;
    #pragma unroll
    for (int i = 0; i < 32; i += 8)
        o[(size_t)(bx + threadIdx.y + i) * R + xo] = rna(t[threadIdx.x][threadIdx.y + i]);
}

// ---------------- RMSNorm (rna-rounded) ----------------
__global__ void rmsnorm_kernel(const float* __restrict__ x,
                               const float* __restrict__ scale,
                               float* __restrict__ out) {
    int row = blockIdx.x;
    int t = threadIdx.x;
    const float4* xr = (const float4*)(x + (size_t)row * D_);
    float4 v = xr[t];
    float ss = v.x*v.x + v.y*v.y + v.z*v.z + v.w*v.w;
    #pragma unroll
    for (int o = 16; o; o >>= 1) ss += __shfl_xor_sync(0xffffffffu, ss, o);
    __shared__ float red[8];
    if ((t & 31) == 0) red[t >> 5] = ss;
    __syncthreads();
    if (t < 8) {
        float s2 = red[t];
        s2 += __shfl_xor_sync(0xffu, s2, 4);
        s2 += __shfl_xor_sync(0xffu, s2, 2);
        s2 += __shfl_xor_sync(0xffu, s2, 1);
        if (t == 0) red[0] = s2;
    }
    __syncthreads();
    float inv = rsqrtf(red[0] * (1.0f / D_) + 1e-6f);
    float4 s4 = ((const float4*)scale)[t];
    float4 o4;
    o4.x = rna(v.x * inv * s4.x);
    o4.y = rna(v.y * inv * s4.y);
    o4.z = rna(v.z * inv * s4.z);
    o4.w = rna(v.w * inv * s4.w);
    ((float4*)(out + (size_t)row * D_))[t] = o4;
}

// ---------------- fused RoPE for q and k inside qkv buffer ----------------
__global__ void rope_kernel(float* __restrict__ qkv, const int* __restrict__ pos) {
    int idx = blockIdx.x * 256 + threadIdx.x;   // NT*H*32*2
    int i = idx & 31;
    int h = (idx >> 5) & (H_ - 1);
    int which = (idx >> 9) & 1;                 // 0=q, 1=k
    int t = idx >> 10;
    float scale = which ? 1.0f : 0.125f;
    float p = (float)pos[t];
    float frac = (float)(2 * i) / (float)HD_;
    float ts = powf(10000.0f, frac);
    float ang = p / ts;
    float sn, cs;
    sincosf(ang, &sn, &cs);
    float* base = qkv + (size_t)t * SD_ + which * D_ + h * HD_;
    float x1 = base[i], x2 = base[i + 32];
    base[i]      = rna((x1 * cs - x2 * sn) * scale);
    base[i + 32] = rna((x2 * cs + x1 * sn) * scale);
}

// ---------------- causal flash attention (tf32 mma.sync), qkv-strided ----------------
#define FSMEM ((128*64 + 64*64 + 64*64 + 128*64) * 4)   // 98304 B

__global__ __launch_bounds__(128)
void flash_mma(const float* __restrict__ qkv, float* __restrict__ O) {
    extern __shared__ float fsm[];
    float* Qs = fsm;
    float* Ks = fsm + 8192;
    float* Vt = fsm + 12288;
    float* Ps = fsm + 16384;
    const uint32_t QSa = sm_u32(Qs), KSa = sm_u32(Ks),
                   VTa = sm_u32(Vt), PSa = sm_u32(Ps);

    const int qt = gridDim.x - 1 - blockIdx.x;
    const int bh = blockIdx.y;
    const int b = bh >> 4, h = bh & 15;
    const int tid = threadIdx.x, lane = tid & 31, warp = tid >> 5;
    const int qbase = qt * 128;
    const int wq = warp * 32;

    const float* Qg = qkv + ((size_t)(b * S_ + qbase)) * SD_ + h * HD_;
    #pragma unroll
    for (int i = 0; i < 16; i++) {
        int ch = tid + 128 * i;
        int r = ch >> 4, c = ch & 15;
        uint32_t sw = (c & 8) | ((c & 7) ^ (r & 7));
        *(float4*)(Qs + r * 64 + sw * 4) = *(const float4*)(Qg + (size_t)r * SD_ + c * 4);
    }

    const int q4 = lane >> 3, r8 = lane & 7;
    const int qh = q4 >> 1, ql = q4 & 1;
    int aR[2], bR[4];
    #pragma unroll
    for (int mf = 0; mf < 2; mf++) aR[mf] = wq + mf * 16 + ql * 8 + r8;
    #pragma unroll
    for (int f2 = 0; f2 < 4; f2++) bR[f2] = f2 * 16 + ql * 8 + r8;

    float m_i[2][2], l_i[2][2], acc[2][8][4];
    #pragma unroll
    for (int mf = 0; mf < 2; mf++) {
        m_i[mf][0] = m_i[mf][1] = -3.0e38f;
        l_i[mf][0] = l_i[mf][1] = 0.f;
        #pragma unroll
        for (int nf = 0; nf < 8; nf++)
            #pragma unroll
            for (int c = 0; c < 4; c++) acc[mf][nf][c] = 0.f;
    }

    const int rlo = lane >> 2;
    const int cq  = (lane & 3) * 2;

    const int jmax = 2 * qt + 1;
    for (int jt = 0; jt <= jmax; jt++) {
        const int kbase = jt * 64;
        __syncthreads();
        const float* Kg = qkv + ((size_t)(b * S_ + kbase)) * SD_ + D_ + h * HD_;
        const float* Vg = qkv + ((size_t)(b * S_ + kbase)) * SD_ + 2 * D_ + h * HD_;
        #pragma unroll
        for (int i = 0; i < 8; i++) {
            int ch = tid + 128 * i;
            int r = ch >> 4, c = ch & 15;
            uint32_t sw = (c & 8) | ((c & 7) ^ (r & 7));
            *(float4*)(Ks + r * 64 + sw * 4) = *(const float4*)(Kg + (size_t)r * SD_ + c * 4);
            float4 vv = *(const float4*)(Vg + (size_t)r * SD_ + c * 4);
            int d4 = c * 4, kk = r;
            int kc = kk >> 2, km = kk & 3;
            #pragma unroll
            for (int j = 0; j < 4; j++) {
                int d = d4 + j;
                uint32_t swv = (uint32_t)((kc & 8) | ((kc & 7) ^ (d & 7)));
                Vt[d * 64 + swv * 4 + km] = rna(j == 0 ? vv.x : j == 1 ? vv.y : j == 2 ? vv.z : vv.w);
            }
        }
        __syncthreads();

        float sa[2][8][4];
        #pragma unroll
        for (int mf = 0; mf < 2; mf++)
            #pragma unroll
            for (int nf = 0; nf < 8; nf++)
                #pragma unroll
                for (int c = 0; c < 4; c++) sa[mf][nf][c] = 0.f;

        #pragma unroll
        for (int s = 0; s < 8; s++) {
            uint32_t af[2][4], bf[8][2];
            #pragma unroll
            for (int mf = 0; mf < 2; mf++) {
                uint32_t sw = (uint32_t)((((2*s+qh) & 8)) | (((2*s+qh) & 7) ^ (aR[mf] & 7)));
                ldm_x4(af[mf][0], af[mf][1], af[mf][2], af[mf][3],
                       QSa + (uint32_t)aR[mf] * 256 + sw * 16);
            }
            #pragma unroll
            for (int f2 = 0; f2 < 4; f2++) {
                uint32_t sw = (uint32_t)((((2*s+qh) & 8)) | (((2*s+qh) & 7) ^ (bR[f2] & 7)));
                ldm_x4(bf[2*f2][0], bf[2*f2+1][0], bf[2*f2][1], bf[2*f2+1][1],
                       KSa + (uint32_t)bR[f2] * 256 + sw * 16);
            }
            #pragma unroll
            for (int mf = 0; mf < 2; mf++)
                #pragma unroll
                for (int nf = 0; nf < 8; nf++)
                    mma_tf32(sa[mf][nf], af[mf], bf[nf]);
        }

        if (jt >= 2 * qt) {
            #pragma unroll
            for (int mf = 0; mf < 2; mf++) {
                int q0 = qbase + wq + mf * 16 + rlo;
                #pragma unroll
                for (int nf = 0; nf < 8; nf++) {
                    int k0 = kbase + nf * 8 + cq;
                    if (k0     > q0    ) sa[mf][nf][0] = -1.0e30f;
                    if (k0 + 1 > q0    ) sa[mf][nf][1] = -1.0e30f;
                    if (k0     > q0 + 8) sa[mf][nf][2] = -1.0e30f;
                    if (k0 + 1 > q0 + 8) sa[mf][nf][3] = -1.0e30f;
                }
            }
        }

        #pragma unroll
        for (int mf = 0; mf < 2; mf++) {
            float mx0 = -3.0e38f, mx1 = -3.0e38f;
            #pragma unroll
            for (int nf = 0; nf < 8; nf++) {
                mx0 = fmaxf(mx0, fmaxf(sa[mf][nf][0], sa[mf][nf][1]));
                mx1 = fmaxf(mx1, fmaxf(sa[mf][nf][2], sa[mf][nf][3]));
            }
            mx0 = fmaxf(mx0, __shfl_xor_sync(0xffffffffu, mx0, 1));
            mx0 = fmaxf(mx0, __shfl_xor_sync(0xffffffffu, mx0, 2));
            mx1 = fmaxf(mx1, __shfl_xor_sync(0xffffffffu, mx1, 1));
            mx1 = fmaxf(mx1, __shfl_xor_sync(0xffffffffu, mx1, 2));
            float mn0 = fmaxf(m_i[mf][0], mx0);
            float mn1 = fmaxf(m_i[mf][1], mx1);
            float cr0 = __expf(m_i[mf][0] - mn0);
            float cr1 = __expf(m_i[mf][1] - mn1);
            m_i[mf][0] = mn0; m_i[mf][1] = mn1;

            int row0 = wq + mf * 16 + rlo;
            int row1 = row0 + 8;
            float rs0 = 0.f, rs1 = 0.f;
            #pragma unroll
            for (int nf = 0; nf < 8; nf++) {
                float p0 = rna(__expf(sa[mf][nf][0] - mn0));
                float p1 = rna(__expf(sa[mf][nf][1] - mn0));
                float p2 = rna(__expf(sa[mf][nf][2] - mn1));
                float p3 = rna(__expf(sa[mf][nf][3] - mn1));
                rs0 += p0 + p1;
                rs1 += p2 + p3;
                int colc = nf * 2 + ((lane & 3) >> 1);
                int cmod = ((lane & 3) & 1) * 2;
                uint32_t sw0 = (uint32_t)((colc & 8) | ((colc & 7) ^ (row0 & 7)));
                uint32_t sw1 = (uint32_t)((colc & 8) | ((colc & 7) ^ (row1 & 7)));
                *(float2*)(Ps + row0 * 64 + sw0 * 4 + cmod) = make_float2(p0, p1);
                *(float2*)(Ps + row1 * 64 + sw1 * 4 + cmod) = make_float2(p2, p3);
            }
            rs0 += __shfl_xor_sync(0xffffffffu, rs0, 1);
            rs0 += __shfl_xor_sync(0xffffffffu, rs0, 2);
            rs1 += __shfl_xor_sync(0xffffffffu, rs1, 1);
            rs1 += __shfl_xor_sync(0xffffffffu, rs1, 2);
            l_i[mf][0] = l_i[mf][0] * cr0 + rs0;
            l_i[mf][1] = l_i[mf][1] * cr1 + rs1;
            #pragma unroll
            for (int nf = 0; nf < 8; nf++) {
                acc[mf][nf][0] *= cr0; acc[mf][nf][1] *= cr0;
                acc[mf][nf][2] *= cr1; acc[mf][nf][3] *= cr1;
            }
        }
        __syncwarp();

        #pragma unroll
        for (int s = 0; s < 8; s++) {
            uint32_t af[2][4], bf[8][2];
            #pragma unroll
            for (int mf = 0; mf < 2; mf++) {
                uint32_t sw = (uint32_t)((((2*s+qh) & 8)) | (((2*s+qh) & 7) ^ (aR[mf] & 7)));
                ldm_x4(af[mf][0], af[mf][1], af[mf][2], af[mf][3],
                       PSa + (uint32_t)aR[mf] * 256 + sw * 16);
            }
            #pragma unroll
            for (int f2 = 0; f2 < 4; f2++) {
                uint32_t sw = (uint32_t)((((2*s+qh) & 8)) | (((2*s+qh) & 7) ^ (bR[f2] & 7)));
                ldm_x4(bf[2*f2][0], bf[2*f2+1][0], bf[2*f2][1], bf[2*f2+1][1],
                       VTa + (uint32_t)bR[f2] * 256 + sw * 16);
            }
            #pragma unroll
            for (int mf = 0; mf < 2; mf++)
                #pragma unroll
                for (int nf = 0; nf < 8; nf++)
                    mma_tf32(acc[mf][nf], af[mf], bf[nf]);
        }
    }

    #pragma unroll
    for (int mf = 0; mf < 2; mf++) {
        float inv0 = 1.0f / l_i[mf][0];
        float inv1 = 1.0f / l_i[mf][1];
        int row0 = qbase + wq + mf * 16 + rlo;
        float* O0 = O + ((size_t)(b * S_ + row0)) * D_ + h * HD_;
        float* O1 = O + ((size_t)(b * S_ + row0 + 8)) * D_ + h * HD_;
        #pragma unroll
        for (int nf = 0; nf < 8; nf++) {
            int col = nf * 8 + cq;
            *(float2*)(O0 + col) = make_float2(rna(acc[mf][nf][0] * inv0),
                                               rna(acc[mf][nf][1] * inv0));
            *(float2*)(O1 + col) = make_float2(rna(acc[mf][nf][2] * inv1),
                                               rna(acc[mf][nf][3] * inv1));
        }
    }
}

// ---------------- gelu(G)*U over fused GU buffer ----------------
__global__ void gelu_mul_kernel(const float* __restrict__ GU, float* __restrict__ Out) {
    int i = blockIdx.x * 256 + threadIdx.x;     // NT*F/4 threads
    int t = i >> 10;                            // F/4 = 1024 float4 per row half
    int j = i & 1023;
    float4 g = ((const float4*)GU)[(size_t)t * 2048 + j];
    float4 u = ((const float4*)GU)[(size_t)t * 2048 + 1024 + j];
    const float c0 = 0.7978845608028654f;
    const float c1 = 0.044715f;
    float4 o;
    o.x = rna(0.5f * g.x * (1.f + tanhf(c0 * (g.x + c1 * g.x * g.x * g.x))) * u.x);
    o.y = rna(0.5f * g.y * (1.f + tanhf(c0 * (g.y + c1 * g.y * g.y * g.y))) * u.y);
    o.z = rna(0.5f * g.z * (1.f + tanhf(c0 * (g.z + c1 * g.z * g.z * g.z))) * u.z);
    o.w = rna(0.5f * g.w * (1.f + tanhf(c0 * (g.w + c1 * g.w * g.w * g.w))) * u.w);
    ((float4*)Out)[i] = o;
}

// ---------------- launch ----------------
extern "C" void kernel_launch(void* const* d_in, const int* in_sizes, int n_in,
                              void* d_out, int out_size) {
    const float* x   = (const float*)d_in[0];
    const int*   sp  = (const int*)  d_in[1];
    const float* wq  = (const float*)d_in[3];
    const float* wk  = (const float*)d_in[4];
    const float* wv  = (const float*)d_in[5];
    const float* wo  = (const float*)d_in[6];
    const float* wg  = (const float*)d_in[7];
    const float* wu  = (const float*)d_in[8];
    const float* wd  = (const float*)d_in[9];
    const float* n1  = (const float*)d_in[10];
    const float* n2  = (const float*)d_in[11];
    float* out = (float*)d_out;

    float *h, *qkv, *ctx, *GU, *G, *wT;
    cudaGetSymbolAddress((void**)&h,   g_h);
    cudaGetSymbolAddress((void**)&qkv, g_qkv);
    cudaGetSymbolAddress((void**)&ctx, g_ctx);
    cudaGetSymbolAddress((void**)&GU,  g_GU);
    cudaGetSymbolAddress((void**)&G,   g_G);
    cudaGetSymbolAddress((void**)&wT,  g_wT);

    float* wqkvoT = wT;                           // [4*D][D]: wqT|wkT|wvT|woT
    float* woT    = wT + (size_t)3 * D_ * D_;
    float* wguT   = wT + (size_t)4 * D_ * D_;     // [2*F][D]: wgT|wuT
    float* wdT    = wguT + (size_t)2 * F_ * D_;   // [D][F]

    cudaFuncSetAttribute(mma_gemm<0>, cudaFuncAttributeMaxDynamicSharedMemorySize, DSMEM);
    cudaFuncSetAttribute(mma_gemm<1>, cudaFuncAttributeMaxDynamicSharedMemorySize, DSMEM);
    cudaFuncSetAttribute(flash_mma,   cudaFuncAttributeMaxDynamicSharedMemorySize, FSMEM);

    dim3 tb(32, 8);
    // launch 0: q,k,v,o weight transposes in one batched launch
    transposeN_kernel<<<dim3(D_/32, D_/32, 4), tb>>>(wq, wk, wv, wo, wqkvoT, D_, D_);
    // launch 1
    rmsnorm_kernel<<<NT_, 256>>>(x, n1, h);
    // launch 2: fused QKV GEMM (N = 3072)
    mma_gemm<0><<<dim3(SD_/BN, NT_/BM), 256, DSMEM>>>(h, wqkvoT, nullptr, qkv, NT_, SD_, D_);
    // launch 3: fused rope (q and k)
    rope_kernel<<<NT_ * H_ * 64 / 256, 256>>>(qkv, sp);
    // launch 4
    flash_mma<<<dim3(S_ / 128, B_ * H_), 128, FSMEM>>>(qkv, ctx);
    // launch 5: o-proj + residual (ncu -s 5 captures this)
    mma_gemm<1><<<dim3(D_/BN, NT_/BM), 256, DSMEM>>>(ctx, woT, x, out, NT_, D_, D_);

    // FFN block
    transposeN_kernel<<<dim3(F_/32, D_/32, 2), tb>>>(wg, wu, nullptr, nullptr, wguT, D_, F_);
    rmsnorm_kernel<<<NT_, 256>>>(out, n2, h);
    mma_gemm<0><<<dim3(2*F_/BN, NT_/BM), 256, DSMEM>>>(h, wguT, nullptr, GU, NT_, 2*F_, D_);
    gelu_mul_kernel<<<NT_ * F_ / 1024, 256>>>(GU, G);
    transposeN_kernel<<<dim3(D_/32, F_/32, 1), tb>>>(wd, nullptr, nullptr, nullptr, wdT, F_, D_);
    mma_gemm<1><<<dim3(D_/BN, NT_/BM), 256, DSMEM>>>(G, wdT, out, out, NT_, D_, F_);
}